// round 2
// baseline (speedup 1.0000x reference)
#include <cuda_runtime.h>
#include <cuda_bf16.h>
#include <cfloat>
#include <cstdint>

// ---------------------------------------------------------------------------
// K-means: X [m,128] fp32, centroids_init [128,128] fp32, K=128, 15 iters,
// tol=1e-4, matching the JAX reference's latch semantics and (as closely as
// possible) its fp32 rounding behavior.
// Output: centroids (128*128 floats) followed by clusters (m floats).
// ---------------------------------------------------------------------------

#define KCLUST 128
#define NDIM   128
#define MAXIT  15
#define MAX_M  100352
#define NBLK_ACC 128
#define TAU 2e-3f

__device__ float  g_cent[KCLUST * NDIM];
__device__ float  g_cent_new[KCLUST * NDIM];
__device__ float  g_csqf[KCLUST];
__device__ double g_part[NBLK_ACC][KCLUST * NDIM];   // per-block partial sums
__device__ int    g_counts[KCLUST];
__device__ int    g_clusters[MAX_M];
__device__ float  g_xsq[MAX_M];
__device__ int    g_conv[MAXIT + 1];
__device__ int    g_done;
__device__ int    g_nflag;
__device__ int    g_flag[MAX_M];

// ---------------------------------------------------------------------------
// init: copy centroids + csq (fp64->fp32 correctly rounded), zero flags
// ---------------------------------------------------------------------------
__global__ void init_kernel(const float* __restrict__ c0) {
    int b = blockIdx.x, t = threadIdx.x;
    if (b < 128) {
        int idx = b * 128 + t;
        float v = c0[idx];
        g_cent[idx] = v;
        __shared__ double rb[128];
        rb[t] = (double)v * (double)v;
        __syncthreads();
        #pragma unroll
        for (int o = 64; o; o >>= 1) {
            if (t < o) rb[t] += rb[t + o];
            __syncthreads();
        }
        if (t == 0) g_csqf[b] = (float)rb[0];
    } else {
        if (t < KCLUST) g_counts[t] = 0;
        if (t < MAXIT + 1) g_conv[t] = 0;
        if (t == 0) { g_done = 0; g_nflag = 0; }
    }
}

// ---------------------------------------------------------------------------
// x_sq per point, fp64 accumulate -> correctly rounded fp32. Warp per point.
// ---------------------------------------------------------------------------
__global__ void xsq_kernel(const float* __restrict__ X, int m) {
    int gtid = blockIdx.x * blockDim.x + threadIdx.x;
    int w = gtid >> 5;
    int lane = gtid & 31;
    if (w >= m) return;
    float4 v = *reinterpret_cast<const float4*>(&X[(size_t)w * NDIM + lane * 4]);
    double s = (double)v.x * v.x + (double)v.y * v.y +
               (double)v.z * v.z + (double)v.w * v.w;
    #pragma unroll
    for (int o = 16; o; o >>= 1) s += __shfl_xor_sync(0xFFFFFFFFu, s, o);
    if (lane == 0) g_xsq[w] = (float)s;
}

// ---------------------------------------------------------------------------
// Assignment stage 1: fused SGEMM (X @ C^T) + argmin + near-tie flagging.
// Block: 128 points x 128 clusters, 256 threads, 8x8 register tile.
// ---------------------------------------------------------------------------
#define CT_PITCH 132
#define CT_FLOATS (128 * CT_PITCH)        // 16896
#define XS_FLOATS (2 * 8 * CT_PITCH)      // 2112
#define ASSIGN_SMEM_FLOATS (CT_FLOATS + XS_FLOATS + 128)
#define ASSIGN_SMEM_BYTES (ASSIGN_SMEM_FLOATS * 4)

__global__ void __launch_bounds__(256, 2)
assign_kernel(const float* __restrict__ X, int m) {
    if (*(volatile int*)&g_done) return;

    extern __shared__ float smem[];
    float* Ct  = smem;                       // [k*132 + c]
    float* Xs  = smem + CT_FLOATS;           // [buf*1056 + kk*132 + p]
    float* csq = smem + CT_FLOATS + XS_FLOATS;

    const int tid = threadIdx.x;
    const int tx = tid & 15;          // cluster group
    const int ty = tid >> 4;          // point group
    const int p0 = blockIdx.x * 128;

    // Load all centroids transposed into smem.
    #pragma unroll
    for (int it = 0; it < 16; ++it) {
        int lin = tid + it * 256;                 // 0..4095 float4s
        int c = lin >> 5;
        int k4 = lin & 31;
        float4 v = *reinterpret_cast<const float4*>(&g_cent[c * 128 + k4 * 4]);
        Ct[(k4 * 4 + 0) * CT_PITCH + c] = v.x;
        Ct[(k4 * 4 + 1) * CT_PITCH + c] = v.y;
        Ct[(k4 * 4 + 2) * CT_PITCH + c] = v.z;
        Ct[(k4 * 4 + 3) * CT_PITCH + c] = v.w;
    }
    if (tid < 128) csq[tid] = g_csqf[tid];

    // First X tile prefetch into regs.
    const int pp = tid >> 1;
    const int half = tid & 1;
    int prow = p0 + pp; if (prow >= m) prow = m - 1;
    const float* xrow = &X[(size_t)prow * NDIM + half * 4];
    float4 nxt = *reinterpret_cast<const float4*>(xrow);

    {
        float* dst = &Xs[(half * 4) * CT_PITCH + pp];
        dst[0 * CT_PITCH] = nxt.x; dst[1 * CT_PITCH] = nxt.y;
        dst[2 * CT_PITCH] = nxt.z; dst[3 * CT_PITCH] = nxt.w;
    }
    __syncthreads();

    float acc[8][8];
    #pragma unroll
    for (int i = 0; i < 8; ++i)
        #pragma unroll
        for (int j = 0; j < 8; ++j) acc[i][j] = 0.0f;

    #pragma unroll 1
    for (int s = 0; s < 16; ++s) {
        if (s < 15)
            nxt = *reinterpret_cast<const float4*>(xrow + (s + 1) * 8);

        const int cur = s & 1;
        const float* xb = &Xs[cur * (8 * CT_PITCH)];
        const float* cb = &Ct[(s * 8) * CT_PITCH];
        #pragma unroll
        for (int kk = 0; kk < 8; ++kk) {
            float4 a0 = *reinterpret_cast<const float4*>(xb + kk * CT_PITCH + ty * 8);
            float4 a1 = *reinterpret_cast<const float4*>(xb + kk * CT_PITCH + ty * 8 + 4);
            float4 b0 = *reinterpret_cast<const float4*>(cb + kk * CT_PITCH + tx * 8);
            float4 b1 = *reinterpret_cast<const float4*>(cb + kk * CT_PITCH + tx * 8 + 4);
            float rm[8] = {a0.x, a0.y, a0.z, a0.w, a1.x, a1.y, a1.z, a1.w};
            float rn[8] = {b0.x, b0.y, b0.z, b0.w, b1.x, b1.y, b1.z, b1.w};
            #pragma unroll
            for (int i = 0; i < 8; ++i)
                #pragma unroll
                for (int j = 0; j < 8; ++j)
                    acc[i][j] = fmaf(rm[i], rn[j], acc[i][j]);
        }

        if (s < 15) {
            float* dst = &Xs[((s + 1) & 1) * (8 * CT_PITCH) + (half * 4) * CT_PITCH + pp];
            dst[0 * CT_PITCH] = nxt.x; dst[1 * CT_PITCH] = nxt.y;
            dst[2 * CT_PITCH] = nxt.z; dst[3 * CT_PITCH] = nxt.w;
        }
        __syncthreads();
    }

    // Epilogue: per-thread best + second-best over its 8 clusters per point.
    float* redD = Ct;                  // [p_local*16 + tx]
    int*   redI = (int*)(Ct + 2048);
    float* redS = Ct + 4096;

    #pragma unroll
    for (int i = 0; i < 8; ++i) {
        int p = p0 + ty * 8 + i;
        int pc = (p < m) ? p : (m - 1);
        float xq = g_xsq[pc];
        float bd = FLT_MAX, sd = FLT_MAX; int bc = 0;
        #pragma unroll
        for (int j = 0; j < 8; ++j) {
            int c = tx * 8 + j;
            float d2 = (xq - 2.0f * acc[i][j]) + csq[c];
            if (d2 < bd) { sd = bd; bd = d2; bc = c; }
            else if (d2 < sd) { sd = d2; }
        }
        redD[(ty * 8 + i) * 16 + tx] = bd;
        redI[(ty * 8 + i) * 16 + tx] = bc;
        redS[(ty * 8 + i) * 16 + tx] = sd;
    }
    __syncthreads();

    if (tid < 128) {
        int p = p0 + tid;
        if (p < m) {
            float bd = redD[tid * 16]; int bc = redI[tid * 16];
            float sd = redS[tid * 16];
            #pragma unroll
            for (int t = 1; t < 16; ++t) {
                float d = redD[tid * 16 + t]; int c = redI[tid * 16 + t];
                float s2 = redS[tid * 16 + t];
                if (d < bd || (d == bd && c < bc)) {
                    sd = fminf(bd, fminf(sd, s2));
                    bd = d; bc = c;
                } else {
                    sd = fminf(sd, fminf(d, s2));
                }
            }
            g_clusters[p] = bc;
            if (sd - bd < TAU) {
                int w = atomicAdd(&g_nflag, 1);
                g_flag[w] = p;
            }
        }
    }
}

// ---------------------------------------------------------------------------
// Assignment stage 2: near-tie refinement in fp64, replaying the reference's
// fp32 op sequence (dot correctly rounded, then fp32 sub/add, first-index-wins).
// ---------------------------------------------------------------------------
__global__ void __launch_bounds__(128)
refine_kernel(const float* __restrict__ X) {
    if (*(volatile int*)&g_done) return;
    int n = *(volatile int*)&g_nflag;
    int c = threadIdx.x;
    __shared__ float sD[128];
    __shared__ int   sI[128];

    for (int w = blockIdx.x; w < n; w += gridDim.x) {
        int p = g_flag[w];
        const float* xr = &X[(size_t)p * NDIM];
        const float* cr = &g_cent[c * NDIM];
        double dot = 0.0;
        #pragma unroll 8
        for (int k = 0; k < NDIM; ++k)
            dot += (double)xr[k] * (double)cr[k];
        float dotf = (float)dot;
        float t = g_xsq[p] - 2.0f * dotf;
        float d2 = t + g_csqf[c];

        sD[c] = d2; sI[c] = c;
        __syncthreads();
        #pragma unroll
        for (int o = 64; o; o >>= 1) {
            if (c < o) {
                float d = sD[c + o]; int cc = sI[c + o];
                if (d < sD[c] || (d == sD[c] && cc < sI[c])) { sD[c] = d; sI[c] = cc; }
            }
            __syncthreads();
        }
        if (c == 0) g_clusters[p] = sI[0];
        __syncthreads();
    }
}

// ---------------------------------------------------------------------------
// Segment accumulation: 128 blocks, smem fp64 sums, deterministic partials.
// ---------------------------------------------------------------------------
#define ACCUM_SMEM_BYTES (KCLUST * NDIM * 8 + KCLUST * 4)

__global__ void __launch_bounds__(128)
accum_kernel(const float* __restrict__ X, int m) {
    if (*(volatile int*)&g_done) return;

    extern __shared__ double sm_d[];
    double* ssum = sm_d;                           // 16384 doubles
    int*    scnt = (int*)(sm_d + KCLUST * NDIM);

    const int tid = threadIdx.x;
    for (int i = tid; i < KCLUST * NDIM; i += 128) ssum[i] = 0.0;
    scnt[tid] = 0;
    __syncthreads();

    int chunk = (m + NBLK_ACC - 1) / NBLK_ACC;
    int lo = blockIdx.x * chunk;
    int hi = lo + chunk; if (hi > m) hi = m;

    for (int i = lo; i < hi; ++i) {
        int c = g_clusters[i];
        float x = X[(size_t)i * NDIM + tid];
        ssum[c * NDIM + tid] += (double)x;
        if (tid == 0) scnt[c]++;
    }
    __syncthreads();

    double* part = g_part[blockIdx.x];
    for (int i = tid; i < KCLUST * NDIM; i += 128) part[i] = ssum[i];
    atomicAdd(&g_counts[tid], scnt[tid]);
}

// ---------------------------------------------------------------------------
// Update A: merge partials in fp64 (deterministic), fp32 divide like ref,
// convergence votes, reset counters.
// ---------------------------------------------------------------------------
__global__ void __launch_bounds__(128)
update_a_kernel(int iter) {
    if (*(volatile int*)&g_done) return;
    int k = blockIdx.x, j = threadIdx.x;
    int idx = k * NDIM + j;

    double s = 0.0;
    #pragma unroll 4
    for (int b = 0; b < NBLK_ACC; ++b) s += g_part[b][idx];
    float sf = (float)s;

    int cnt = g_counts[k];
    float old = g_cent[idx];
    float newc = (cnt > 0) ? (sf / fmaxf((float)cnt, 1.0f)) : old;
    g_cent_new[idx] = newc;

    float d = newc - old;
    __shared__ float rb[128];
    rb[j] = d * d;
    __syncthreads();
    #pragma unroll
    for (int o = 64; o; o >>= 1) {
        if (j < o) rb[j] += rb[j + o];
        __syncthreads();
    }
    if (j == 0) {
        if (rb[0] < 1e-8f) atomicAdd(&g_conv[iter], 1);
        g_counts[k] = 0;
        if (k == 0) g_nflag = 0;
    }
}

// ---------------------------------------------------------------------------
// Update B: apply latch; copy centroids and recompute csq (fp64->fp32).
// ---------------------------------------------------------------------------
__global__ void __launch_bounds__(128)
update_b_kernel(int iter) {
    if (*(volatile int*)&g_done) return;
    int k = blockIdx.x, j = threadIdx.x;
    int cv = g_conv[iter];
    if (cv == KCLUST) {
        if (k == 0 && j == 0) g_done = 1;
        return;
    }
    int idx = k * NDIM + j;
    float v = g_cent_new[idx];
    g_cent[idx] = v;

    __shared__ double rb[128];
    rb[j] = (double)v * (double)v;
    __syncthreads();
    #pragma unroll
    for (int o = 64; o; o >>= 1) {
        if (j < o) rb[j] += rb[j + o];
        __syncthreads();
    }
    if (j == 0) g_csqf[k] = (float)rb[0];
}

// ---------------------------------------------------------------------------
// Finalize: pack outputs (centroids first, then clusters as float).
// ---------------------------------------------------------------------------
__global__ void finalize_kernel(float* __restrict__ out, int m, int out_size) {
    int idx = blockIdx.x * 256 + threadIdx.x;
    const int nc = KCLUST * NDIM;
    if (out_size >= nc + m) {
        if (idx < nc) out[idx] = g_cent[idx];
        else if (idx < nc + m) out[idx] = (float)g_clusters[idx - nc];
    } else if (out_size == m) {
        if (idx < m) out[idx] = (float)g_clusters[idx];
    } else {
        if (idx < out_size && idx < nc) out[idx] = g_cent[idx];
    }
}

// ---------------------------------------------------------------------------
extern "C" void kernel_launch(void* const* d_in, const int* in_sizes, int n_in,
                              void* d_out, int out_size) {
    const float* X  = (const float*)d_in[0];
    const float* C0 = (const float*)d_in[1];
    int m = in_sizes[0] / NDIM;
    if (m > MAX_M) m = MAX_M;

    cudaFuncSetAttribute(assign_kernel,
                         cudaFuncAttributeMaxDynamicSharedMemorySize,
                         ASSIGN_SMEM_BYTES);
    cudaFuncSetAttribute(accum_kernel,
                         cudaFuncAttributeMaxDynamicSharedMemorySize,
                         ACCUM_SMEM_BYTES);

    init_kernel<<<129, 128>>>(C0);
    {
        int blocks = (m * 32 + 255) / 256;
        xsq_kernel<<<blocks, 256>>>(X, m);
    }

    int ablocks = (m + 127) / 128;
    for (int it = 0; it < MAXIT; ++it) {
        assign_kernel<<<ablocks, 256, ASSIGN_SMEM_BYTES>>>(X, m);
        refine_kernel<<<128, 128>>>(X);
        accum_kernel<<<NBLK_ACC, 128, ACCUM_SMEM_BYTES>>>(X, m);
        update_a_kernel<<<128, 128>>>(it);
        update_b_kernel<<<128, 128>>>(it);
    }

    int fb = (out_size + 255) / 256;
    if (fb < 1) fb = 1;
    finalize_kernel<<<fb, 256>>>((float*)d_out, m, out_size);
}

// round 3
// speedup vs baseline: 1.0665x; 1.0665x over previous
#include <cuda_runtime.h>
#include <cuda_bf16.h>
#include <cfloat>
#include <cstdint>

// ---------------------------------------------------------------------------
// K-means: X [m,128] fp32, centroids_init [128,128] fp32, K=128, 15 iters,
// tol=1e-4. Assignment via bf16-split tensor-core GEMM (3-pass, ~2^-17 dot
// accuracy) + near-tie fp64 refinement replaying the reference fp32 op order.
// ---------------------------------------------------------------------------

#define KCLUST 128
#define NDIM   128
#define MAXIT  15
#define MAX_M  100352
#define NBLK_ACC 128
#define TAU 4e-3f
#define APITCH 72   // bf16 pitch for smem tiles (conflict-free ldmatrix)

__device__ float  g_cent[KCLUST * NDIM];
__device__ float  g_cent_new[KCLUST * NDIM];
__device__ float  g_csqf[KCLUST];
__device__ double g_part[NBLK_ACC][KCLUST * NDIM];
__device__ int    g_counts[KCLUST];
__device__ int    g_clusters[MAX_M];
__device__ float  g_xsq[MAX_M];
__device__ int    g_conv[MAXIT + 1];
__device__ int    g_done;
__device__ int    g_nflag;
__device__ int    g_flag[MAX_M];

__device__ __nv_bfloat16 g_xhi[MAX_M * NDIM];
__device__ __nv_bfloat16 g_xlo[MAX_M * NDIM];
__device__ __nv_bfloat16 g_chi[KCLUST * NDIM];
__device__ __nv_bfloat16 g_clo[KCLUST * NDIM];

// ---------------------------------------------------------------------------
__global__ void init_kernel(const float* __restrict__ c0) {
    int b = blockIdx.x, t = threadIdx.x;
    if (b < 128) {
        int idx = b * 128 + t;
        float v = c0[idx];
        g_cent[idx] = v;
        __nv_bfloat16 hi = __float2bfloat16(v);
        g_chi[idx] = hi;
        g_clo[idx] = __float2bfloat16(v - __bfloat162float(hi));
        __shared__ double rb[128];
        rb[t] = (double)v * (double)v;
        __syncthreads();
        #pragma unroll
        for (int o = 64; o; o >>= 1) {
            if (t < o) rb[t] += rb[t + o];
            __syncthreads();
        }
        if (t == 0) g_csqf[b] = (float)rb[0];
    } else {
        if (t < KCLUST) g_counts[t] = 0;
        if (t < MAXIT + 1) g_conv[t] = 0;
        if (t == 0) { g_done = 0; g_nflag = 0; }
    }
}

// ---------------------------------------------------------------------------
// One-time: x_sq (fp64->fp32) and bf16 split of X (zero padded tail rows).
// ---------------------------------------------------------------------------
__global__ void xsq_kernel(const float* __restrict__ X, int m) {
    int gtid = blockIdx.x * blockDim.x + threadIdx.x;
    int w = gtid >> 5;
    int lane = gtid & 31;
    if (w >= m) return;
    float4 v = *reinterpret_cast<const float4*>(&X[(size_t)w * NDIM + lane * 4]);
    double s = (double)v.x * v.x + (double)v.y * v.y +
               (double)v.z * v.z + (double)v.w * v.w;
    #pragma unroll
    for (int o = 16; o; o >>= 1) s += __shfl_xor_sync(0xFFFFFFFFu, s, o);
    if (lane == 0) g_xsq[w] = (float)s;
}

__global__ void xsplit_kernel(const float* __restrict__ X, int m) {
    int i = blockIdx.x * 256 + threadIdx.x;
    if (i >= MAX_M * NDIM) return;
    float v = (i < m * NDIM) ? X[i] : 0.0f;
    __nv_bfloat16 hi = __float2bfloat16(v);
    g_xhi[i] = hi;
    g_xlo[i] = __float2bfloat16(v - __bfloat162float(hi));
}

// ---------------------------------------------------------------------------
// Assignment stage 1: bf16-split tensor-core GEMM + argmin + near-tie flags.
// Block: 128 points x 128 clusters, 8 warps, warp tile 32(M) x 64(N).
// ---------------------------------------------------------------------------
#define LDSM_X4(r0, r1, r2, r3, addr) \
    asm volatile("ldmatrix.sync.aligned.m8n8.x4.shared.b16 {%0,%1,%2,%3}, [%4];" \
        : "=r"(r0), "=r"(r1), "=r"(r2), "=r"(r3) : "r"(addr))

#define MMA16816(d, a, b0, b1) \
    asm volatile("mma.sync.aligned.m16n8k16.row.col.f32.bf16.bf16.f32 " \
        "{%0,%1,%2,%3},{%4,%5,%6,%7},{%8,%9},{%0,%1,%2,%3};" \
        : "+f"(d[0]), "+f"(d[1]), "+f"(d[2]), "+f"(d[3]) \
        : "r"(a[0]), "r"(a[1]), "r"(a[2]), "r"(a[3]), "r"(b0), "r"(b1))

#define ASSIGN_TC_SMEM (2 * 128 * APITCH * 2 + 1024)

__global__ void __launch_bounds__(256, 2)
assign_tc_kernel(int m) {
    if (*(volatile int*)&g_done) return;

    extern __shared__ char sm8[];
    __nv_bfloat16* As = (__nv_bfloat16*)sm8;
    __nv_bfloat16* Bs = As + 128 * APITCH;
    float* scs = (float*)(Bs + 128 * APITCH);
    float* sxq = scs + 128;
    // epilogue scratch (reuses As region after final sync)
    float* redD = (float*)sm8;
    int*   redI = (int*)(sm8 + 2048);
    float* redS = (float*)(sm8 + 4096);

    const int tid = threadIdx.x;
    const int lane = tid & 31;
    const int wid = tid >> 5;
    const int wm = wid & 3;       // M tile (32 rows)
    const int wn = wid >> 2;      // N tile (64 cols)
    const int p0 = blockIdx.x * 128;

    if (tid < 128) {
        scs[tid] = g_csqf[tid];
        int p = p0 + tid;
        sxq[tid] = (p < m) ? g_xsq[p] : 0.0f;
    }

    // ldmatrix lane address offsets
    const int q = lane >> 3;
    const int r = lane & 7;
    uint32_t asBase = (uint32_t)__cvta_generic_to_shared(As);
    uint32_t bsBase = (uint32_t)__cvta_generic_to_shared(Bs);
    // A: q0: (r, 0) q1: (r+8, 0) q2: (r, 8) q3: (r+8, 8)
    uint32_t aoff[2];
    #pragma unroll
    for (int mi = 0; mi < 2; ++mi)
        aoff[mi] = asBase +
            (uint32_t)(((wm * 32 + mi * 16 + (q & 1) * 8 + r) * APITCH + (q >> 1) * 8) * 2);
    // B pairs: q0: (r, 0) q1: (r, 8) q2: (r+8, 0) q3: (r+8, 8)
    uint32_t boff[4];
    #pragma unroll
    for (int nip = 0; nip < 4; ++nip)
        boff[nip] = bsBase +
            (uint32_t)(((wn * 64 + nip * 16 + (q >> 1) * 8 + r) * APITCH + (q & 1) * 8) * 2);

    float acc[2][8][4];
    #pragma unroll
    for (int mi = 0; mi < 2; ++mi)
        #pragma unroll
        for (int ni = 0; ni < 8; ++ni)
            #pragma unroll
            for (int u = 0; u < 4; ++u) acc[mi][ni][u] = 0.0f;

    #pragma unroll 1
    for (int pass = 0; pass < 3; ++pass) {
        const __nv_bfloat16* Ap = (pass == 2) ? g_xlo : g_xhi;
        const __nv_bfloat16* Bp = (pass == 1) ? g_clo : g_chi;
        #pragma unroll 1
        for (int kc = 0; kc < 128; kc += 64) {
            __syncthreads();
            #pragma unroll
            for (int i = 0; i < 4; ++i) {
                int lin = tid + i * 256;
                int row = lin >> 3, c8 = lin & 7;
                uint4 va = *(const uint4*)(Ap + (size_t)(p0 + row) * 128 + kc + c8 * 8);
                *(uint4*)(As + row * APITCH + c8 * 8) = va;
                uint4 vb = *(const uint4*)(Bp + row * 128 + kc + c8 * 8);
                *(uint4*)(Bs + row * APITCH + c8 * 8) = vb;
            }
            __syncthreads();
            #pragma unroll
            for (int ks = 0; ks < 4; ++ks) {
                uint32_t a[2][4];
                #pragma unroll
                for (int mi = 0; mi < 2; ++mi)
                    LDSM_X4(a[mi][0], a[mi][1], a[mi][2], a[mi][3],
                            aoff[mi] + ks * 32);
                uint32_t b[4][4];
                #pragma unroll
                for (int nip = 0; nip < 4; ++nip)
                    LDSM_X4(b[nip][0], b[nip][1], b[nip][2], b[nip][3],
                            boff[nip] + ks * 32);
                #pragma unroll
                for (int mi = 0; mi < 2; ++mi)
                    #pragma unroll
                    for (int nip = 0; nip < 4; ++nip) {
                        MMA16816(acc[mi][nip * 2 + 0], a[mi], b[nip][0], b[nip][1]);
                        MMA16816(acc[mi][nip * 2 + 1], a[mi], b[nip][2], b[nip][3]);
                    }
            }
        }
    }
    __syncthreads();

    // Epilogue: d2 + best/second-best per point.
    const int r0 = lane >> 2;          // row within m8
    const int c0 = (lane & 3) * 2;     // col pair within n8
    float bd[4], sd[4]; int bi[4];
    #pragma unroll
    for (int mi = 0; mi < 2; ++mi) {
        #pragma unroll
        for (int h = 0; h < 2; ++h) {
            int qq = mi * 2 + h;
            int pl = wm * 32 + mi * 16 + h * 8 + r0;
            float xq = sxq[pl];
            float b_ = FLT_MAX, s_ = FLT_MAX; int i_ = 0;
            #pragma unroll
            for (int ni = 0; ni < 8; ++ni) {
                #pragma unroll
                for (int u = 0; u < 2; ++u) {
                    int n = wn * 64 + ni * 8 + c0 + u;
                    float d2 = (xq - 2.0f * acc[mi][ni][h * 2 + u]) + scs[n];
                    if (d2 < b_) { s_ = b_; b_ = d2; i_ = n; }
                    else if (d2 < s_) s_ = d2;
                }
            }
            bd[qq] = b_; sd[qq] = s_; bi[qq] = i_;
        }
    }
    // combine across the 4 lanes sharing each row
    #pragma unroll
    for (int off = 1; off <= 2; off <<= 1) {
        #pragma unroll
        for (int qq = 0; qq < 4; ++qq) {
            float obd = __shfl_xor_sync(0xFFFFFFFFu, bd[qq], off);
            int   obi = __shfl_xor_sync(0xFFFFFFFFu, bi[qq], off);
            float osd = __shfl_xor_sync(0xFFFFFFFFu, sd[qq], off);
            bool take = (obd < bd[qq]) || (obd == bd[qq] && obi < bi[qq]);
            float loser = take ? bd[qq] : obd;
            sd[qq] = fminf(fminf(sd[qq], osd), loser);
            if (take) { bd[qq] = obd; bi[qq] = obi; }
        }
    }
    if ((lane & 3) == 0) {
        #pragma unroll
        for (int qq = 0; qq < 4; ++qq) {
            int pl = wm * 32 + (qq >> 1) * 16 + (qq & 1) * 8 + r0;
            redD[pl * 2 + wn] = bd[qq];
            redI[pl * 2 + wn] = bi[qq];
            redS[pl * 2 + wn] = sd[qq];
        }
    }
    __syncthreads();

    if (tid < 128) {
        int p = p0 + tid;
        if (p < m) {
            float b_ = redD[tid * 2], s_ = redS[tid * 2];
            int i_ = redI[tid * 2];
            float od = redD[tid * 2 + 1], os = redS[tid * 2 + 1];
            int oi = redI[tid * 2 + 1];
            bool take = (od < b_) || (od == b_ && oi < i_);
            float loser = take ? b_ : od;
            s_ = fminf(fminf(s_, os), loser);
            if (take) { b_ = od; i_ = oi; }
            g_clusters[p] = i_;
            if (s_ - b_ < TAU) {
                int w = atomicAdd(&g_nflag, 1);
                g_flag[w] = p;
            }
        }
    }
}

// ---------------------------------------------------------------------------
// Stage 2: near-tie refinement in fp64 (correctly-rounded dot), then the
// reference's exact fp32 op sequence, first-index-wins argmin.
// ---------------------------------------------------------------------------
__global__ void __launch_bounds__(128)
refine_kernel(const float* __restrict__ X) {
    if (*(volatile int*)&g_done) return;
    int n = *(volatile int*)&g_nflag;
    int c = threadIdx.x;
    __shared__ float sD[128];
    __shared__ int   sI[128];

    for (int w = blockIdx.x; w < n; w += gridDim.x) {
        int p = g_flag[w];
        const float* xr = &X[(size_t)p * NDIM];
        const float* cr = &g_cent[c * NDIM];
        double ac[8] = {0, 0, 0, 0, 0, 0, 0, 0};
        #pragma unroll
        for (int k = 0; k < 16; ++k)
            #pragma unroll
            for (int j = 0; j < 8; ++j)
                ac[j] += (double)xr[k * 8 + j] * (double)cr[k * 8 + j];
        double dot = ((ac[0] + ac[1]) + (ac[2] + ac[3])) +
                     ((ac[4] + ac[5]) + (ac[6] + ac[7]));
        float dotf = (float)dot;
        float t = g_xsq[p] - 2.0f * dotf;
        float d2 = t + g_csqf[c];

        sD[c] = d2; sI[c] = c;
        __syncthreads();
        #pragma unroll
        for (int o = 64; o; o >>= 1) {
            if (c < o) {
                float d = sD[c + o]; int cc = sI[c + o];
                if (d < sD[c] || (d == sD[c] && cc < sI[c])) { sD[c] = d; sI[c] = cc; }
            }
            __syncthreads();
        }
        if (c == 0) g_clusters[p] = sI[0];
        __syncthreads();
    }
}

// ---------------------------------------------------------------------------
// Segment accumulation: smem fp64 sums, deterministic per-block partials.
// ---------------------------------------------------------------------------
#define ACCUM_SMEM_BYTES (KCLUST * NDIM * 8 + KCLUST * 4)

__global__ void __launch_bounds__(128)
accum_kernel(const float* __restrict__ X, int m) {
    if (*(volatile int*)&g_done) return;

    extern __shared__ double sm_d[];
    double* ssum = sm_d;
    int*    scnt = (int*)(sm_d + KCLUST * NDIM);

    const int tid = threadIdx.x;
    for (int i = tid; i < KCLUST * NDIM; i += 128) ssum[i] = 0.0;
    scnt[tid] = 0;
    __syncthreads();

    int chunk = (m + NBLK_ACC - 1) / NBLK_ACC;
    int lo = blockIdx.x * chunk;
    int hi = lo + chunk; if (hi > m) hi = m;

    for (int i = lo; i < hi; ++i) {
        int c = g_clusters[i];
        float x = X[(size_t)i * NDIM + tid];
        ssum[c * NDIM + tid] += (double)x;
        if (tid == 0) scnt[c]++;
    }
    __syncthreads();

    double* part = g_part[blockIdx.x];
    for (int i = tid; i < KCLUST * NDIM; i += 128) part[i] = ssum[i];
    atomicAdd(&g_counts[tid], scnt[tid]);
}

// ---------------------------------------------------------------------------
__global__ void __launch_bounds__(128)
update_a_kernel(int iter) {
    if (*(volatile int*)&g_done) return;
    int k = blockIdx.x, j = threadIdx.x;
    int idx = k * NDIM + j;

    double s = 0.0;
    #pragma unroll 4
    for (int b = 0; b < NBLK_ACC; ++b) s += g_part[b][idx];
    float sf = (float)s;

    int cnt = g_counts[k];
    float old = g_cent[idx];
    float newc = (cnt > 0) ? (sf / fmaxf((float)cnt, 1.0f)) : old;
    g_cent_new[idx] = newc;

    float d = newc - old;
    __shared__ float rb[128];
    rb[j] = d * d;
    __syncthreads();
    #pragma unroll
    for (int o = 64; o; o >>= 1) {
        if (j < o) rb[j] += rb[j + o];
        __syncthreads();
    }
    if (j == 0) {
        if (rb[0] < 1e-8f) atomicAdd(&g_conv[iter], 1);
        g_counts[k] = 0;
        if (k == 0) g_nflag = 0;
    }
}

__global__ void __launch_bounds__(128)
update_b_kernel(int iter) {
    if (*(volatile int*)&g_done) return;
    int k = blockIdx.x, j = threadIdx.x;
    int cv = g_conv[iter];
    if (cv == KCLUST) {
        if (k == 0 && j == 0) g_done = 1;
        return;
    }
    int idx = k * NDIM + j;
    float v = g_cent_new[idx];
    g_cent[idx] = v;
    __nv_bfloat16 hi = __float2bfloat16(v);
    g_chi[idx] = hi;
    g_clo[idx] = __float2bfloat16(v - __bfloat162float(hi));

    __shared__ double rb[128];
    rb[j] = (double)v * (double)v;
    __syncthreads();
    #pragma unroll
    for (int o = 64; o; o >>= 1) {
        if (j < o) rb[j] += rb[j + o];
        __syncthreads();
    }
    if (j == 0) g_csqf[k] = (float)rb[0];
}

// ---------------------------------------------------------------------------
__global__ void finalize_kernel(float* __restrict__ out, int m, int out_size) {
    int idx = blockIdx.x * 256 + threadIdx.x;
    const int nc = KCLUST * NDIM;
    if (out_size >= nc + m) {
        if (idx < nc) out[idx] = g_cent[idx];
        else if (idx < nc + m) out[idx] = (float)g_clusters[idx - nc];
    } else if (out_size == m) {
        if (idx < m) out[idx] = (float)g_clusters[idx];
    } else {
        if (idx < out_size && idx < nc) out[idx] = g_cent[idx];
    }
}

// ---------------------------------------------------------------------------
extern "C" void kernel_launch(void* const* d_in, const int* in_sizes, int n_in,
                              void* d_out, int out_size) {
    const float* X  = (const float*)d_in[0];
    const float* C0 = (const float*)d_in[1];
    int m = in_sizes[0] / NDIM;
    if (m > MAX_M) m = MAX_M;

    cudaFuncSetAttribute(assign_tc_kernel,
                         cudaFuncAttributeMaxDynamicSharedMemorySize,
                         ASSIGN_TC_SMEM);
    cudaFuncSetAttribute(accum_kernel,
                         cudaFuncAttributeMaxDynamicSharedMemorySize,
                         ACCUM_SMEM_BYTES);

    init_kernel<<<129, 128>>>(C0);
    xsq_kernel<<<(m * 32 + 255) / 256, 256>>>(X, m);
    xsplit_kernel<<<(MAX_M * NDIM + 255) / 256, 256>>>(X, m);

    int ablocks = (m + 127) / 128;
    for (int it = 0; it < MAXIT; ++it) {
        assign_tc_kernel<<<ablocks, 256, ASSIGN_TC_SMEM>>>(m);
        refine_kernel<<<256, 128>>>(X);
        accum_kernel<<<NBLK_ACC, 128, ACCUM_SMEM_BYTES>>>(X, m);
        update_a_kernel<<<128, 128>>>(it);
        update_b_kernel<<<128, 128>>>(it);
    }

    int fb = (out_size + 255) / 256;
    if (fb < 1) fb = 1;
    finalize_kernel<<<fb, 256>>>((float*)d_out, m, out_size);
}

// round 4
// speedup vs baseline: 1.2315x; 1.1547x over previous
#include <cuda_runtime.h>
#include <cuda_bf16.h>
#include <cfloat>
#include <cstdint>

// ---------------------------------------------------------------------------
// K-means: X [m,128] fp32, centroids_init [128,128] fp32, K=128, 15 iters,
// tol=1e-4. Assignment via bf16-split tensor-core GEMM (3 logical passes,
// ~2^-17 dot accuracy) + near-tie fp64 refinement replaying the reference
// fp32 op order. Segment sums in fp64 (deterministic).
// ---------------------------------------------------------------------------

#define KCLUST 128
#define NDIM   128
#define MAXIT  15
#define MAX_M  100352
#define NBLK_ACC 256
#define TAU 4e-3f
#define APITCH 72   // bf16 pitch for 64-col smem tiles (conflict-free ldmatrix)

__device__ float  g_cent[KCLUST * NDIM];
__device__ float  g_cent_new[KCLUST * NDIM];
__device__ float  g_csqf[KCLUST];
__device__ double g_part[NBLK_ACC][KCLUST * NDIM];
__device__ int    g_counts[KCLUST];
__device__ int    g_clusters[MAX_M];
__device__ float  g_xsq[MAX_M];
__device__ int    g_conv[MAXIT + 1];
__device__ int    g_done;
__device__ int    g_nflag;
__device__ int    g_flag[MAX_M];

__device__ __nv_bfloat16 g_xhi[MAX_M * NDIM];
__device__ __nv_bfloat16 g_xlo[MAX_M * NDIM];
__device__ __nv_bfloat16 g_chi[KCLUST * NDIM];
__device__ __nv_bfloat16 g_clo[KCLUST * NDIM];

// ---------------------------------------------------------------------------
__global__ void init_kernel(const float* __restrict__ c0) {
    int b = blockIdx.x, t = threadIdx.x;
    if (b < 128) {
        int idx = b * 128 + t;
        float v = c0[idx];
        g_cent[idx] = v;
        __nv_bfloat16 hi = __float2bfloat16(v);
        g_chi[idx] = hi;
        g_clo[idx] = __float2bfloat16(v - __bfloat162float(hi));
        __shared__ double rb[128];
        rb[t] = (double)v * (double)v;
        __syncthreads();
        #pragma unroll
        for (int o = 64; o; o >>= 1) {
            if (t < o) rb[t] += rb[t + o];
            __syncthreads();
        }
        if (t == 0) g_csqf[b] = (float)rb[0];
    } else {
        if (t < KCLUST) g_counts[t] = 0;
        if (t < MAXIT + 1) g_conv[t] = 0;
        if (t == 0) { g_done = 0; g_nflag = 0; }
    }
}

// ---------------------------------------------------------------------------
// One-time: fused x_sq (fp64->fp32) + bf16 split of X (+ zero padded rows).
// One warp per row, 8 rows per block.
// ---------------------------------------------------------------------------
__global__ void __launch_bounds__(256)
xprep_kernel(const float* __restrict__ X, int m) {
    int row = blockIdx.x * 8 + (threadIdx.x >> 5);
    int lane = threadIdx.x & 31;
    if (row >= MAX_M) return;
    __nv_bfloat162* hip = (__nv_bfloat162*)(g_xhi + (size_t)row * NDIM + lane * 4);
    __nv_bfloat162* lop = (__nv_bfloat162*)(g_xlo + (size_t)row * NDIM + lane * 4);
    if (row < m) {
        float4 v = *reinterpret_cast<const float4*>(&X[(size_t)row * NDIM + lane * 4]);
        float f[4] = {v.x, v.y, v.z, v.w};
        __nv_bfloat16 h[4], l[4];
        #pragma unroll
        for (int j = 0; j < 4; ++j) {
            h[j] = __float2bfloat16(f[j]);
            l[j] = __float2bfloat16(f[j] - __bfloat162float(h[j]));
        }
        hip[0] = __nv_bfloat162(h[0], h[1]);
        hip[1] = __nv_bfloat162(h[2], h[3]);
        lop[0] = __nv_bfloat162(l[0], l[1]);
        lop[1] = __nv_bfloat162(l[2], l[3]);
        double s = (double)v.x * v.x + (double)v.y * v.y +
                   (double)v.z * v.z + (double)v.w * v.w;
        #pragma unroll
        for (int o = 16; o; o >>= 1) s += __shfl_xor_sync(0xFFFFFFFFu, s, o);
        if (lane == 0) g_xsq[row] = (float)s;
    } else {
        __nv_bfloat162 z(__float2bfloat16(0.0f), __float2bfloat16(0.0f));
        hip[0] = z; hip[1] = z; lop[0] = z; lop[1] = z;
    }
}

// ---------------------------------------------------------------------------
// Assignment stage 1: bf16-split tensor-core GEMM + argmin + near-tie flags.
// All 4 centroid chunks (hi0,hi1,lo0,lo1) smem-resident; A staged 4x:
//   s0: xhi kc0 x {Chi0, Clo0}   s1: xhi kc64 x {Chi1, Clo1}
//   s2: xlo kc0 x Chi0           s3: xlo kc64 x Chi1
// ---------------------------------------------------------------------------
#define LDSM_X4(r0, r1, r2, r3, addr) \
    asm volatile("ldmatrix.sync.aligned.m8n8.x4.shared.b16 {%0,%1,%2,%3}, [%4];" \
        : "=r"(r0), "=r"(r1), "=r"(r2), "=r"(r3) : "r"(addr))

#define MMA16816(d, a, b0, b1) \
    asm volatile("mma.sync.aligned.m16n8k16.row.col.f32.bf16.bf16.f32 " \
        "{%0,%1,%2,%3},{%4,%5,%6,%7},{%8,%9},{%0,%1,%2,%3};" \
        : "+f"(d[0]), "+f"(d[1]), "+f"(d[2]), "+f"(d[3]) \
        : "r"(a[0]), "r"(a[1]), "r"(a[2]), "r"(a[3]), "r"(b0), "r"(b1))

#define TILE_B (128 * APITCH)                 // bf16 elements per chunk tile
#define ASSIGN_TC_SMEM ((4 + 2) * TILE_B * 2 + 1024)

__global__ void __launch_bounds__(256, 2)
assign_tc_kernel(int m) {
    if (*(volatile int*)&g_done) return;

    extern __shared__ char sm8[];
    __nv_bfloat16* Cs = (__nv_bfloat16*)sm8;         // 4 chunks
    __nv_bfloat16* As = Cs + 4 * TILE_B;             // 2 buffers
    float* scs = (float*)(As + 2 * TILE_B);
    float* sxq = scs + 128;
    // epilogue scratch (overlays Cs after final sync)
    float* redD = (float*)sm8;
    int*   redI = (int*)(sm8 + 2048);
    float* redS = (float*)(sm8 + 4096);

    const int tid = threadIdx.x;
    const int lane = tid & 31;
    const int wid = tid >> 5;
    const int wm = wid & 3;       // M tile (32 rows)
    const int wn = wid >> 2;      // N tile (64 cols)
    const int p0 = blockIdx.x * 128;

    if (tid < 128) {
        scs[tid] = g_csqf[tid];
        int p = p0 + tid;
        sxq[tid] = (p < m) ? g_xsq[p] : 0.0f;
    }

    // Load all 4 centroid chunks: ch = {chi kc0, chi kc64, clo kc0, clo kc64}.
    #pragma unroll
    for (int ch = 0; ch < 4; ++ch) {
        const __nv_bfloat16* Bp = (ch < 2) ? g_chi : g_clo;
        int kc = (ch & 1) * 64;
        #pragma unroll
        for (int i = 0; i < 4; ++i) {
            int lin = tid + i * 256;
            int row = lin >> 3, c8 = lin & 7;
            uint4 vb = *(const uint4*)(Bp + row * 128 + kc + c8 * 8);
            *(uint4*)(Cs + ch * TILE_B + row * APITCH + c8 * 8) = vb;
        }
    }

    // Prefetch A stage 0 (xhi, kc0) into regs + stage it.
    uint4 nxt[4];
    {
        const __nv_bfloat16* Ap = g_xhi;
        #pragma unroll
        for (int i = 0; i < 4; ++i) {
            int lin = tid + i * 256;
            int row = lin >> 3, c8 = lin & 7;
            nxt[i] = *(const uint4*)(Ap + (size_t)(p0 + row) * 128 + c8 * 8);
        }
        #pragma unroll
        for (int i = 0; i < 4; ++i) {
            int lin = tid + i * 256;
            int row = lin >> 3, c8 = lin & 7;
            *(uint4*)(As + row * APITCH + c8 * 8) = nxt[i];
        }
    }
    __syncthreads();

    // ldmatrix lane address offsets
    const int q = lane >> 3;
    const int r = lane & 7;
    uint32_t asBase = (uint32_t)__cvta_generic_to_shared(As);
    uint32_t csBase = (uint32_t)__cvta_generic_to_shared(Cs);
    uint32_t aoff[2];
    #pragma unroll
    for (int mi = 0; mi < 2; ++mi)
        aoff[mi] = asBase +
            (uint32_t)(((wm * 32 + mi * 16 + (q & 1) * 8 + r) * APITCH + (q >> 1) * 8) * 2);
    uint32_t boff[4];
    #pragma unroll
    for (int nip = 0; nip < 4; ++nip)
        boff[nip] = csBase +
            (uint32_t)(((wn * 64 + nip * 16 + (q >> 1) * 8 + r) * APITCH + (q & 1) * 8) * 2);

    float acc[2][8][4];
    #pragma unroll
    for (int mi = 0; mi < 2; ++mi)
        #pragma unroll
        for (int ni = 0; ni < 8; ++ni)
            #pragma unroll
            for (int u = 0; u < 4; ++u) acc[mi][ni][u] = 0.0f;

    const uint32_t TILE_BYTES = TILE_B * 2;

    #pragma unroll 1
    for (int s = 0; s < 4; ++s) {
        // prefetch next A stage
        if (s < 3) {
            const __nv_bfloat16* Ap = (s + 1 < 2) ? g_xhi : g_xlo;
            int kc = ((s + 1) & 1) * 64;
            #pragma unroll
            for (int i = 0; i < 4; ++i) {
                int lin = tid + i * 256;
                int row = lin >> 3, c8 = lin & 7;
                nxt[i] = *(const uint4*)(Ap + (size_t)(p0 + row) * 128 + kc + c8 * 8);
            }
        }

        const uint32_t abuf = (uint32_t)(s & 1) * TILE_BYTES;
        const uint32_t hiB = (uint32_t)(s & 1) * TILE_BYTES;
        const uint32_t loB = (uint32_t)(2 + (s & 1)) * TILE_BYTES;
        const bool doLo = (s < 2);

        #pragma unroll
        for (int ks = 0; ks < 4; ++ks) {
            uint32_t a[2][4];
            #pragma unroll
            for (int mi = 0; mi < 2; ++mi)
                LDSM_X4(a[mi][0], a[mi][1], a[mi][2], a[mi][3],
                        aoff[mi] + abuf + ks * 32);
            uint32_t b[4][4];
            #pragma unroll
            for (int nip = 0; nip < 4; ++nip)
                LDSM_X4(b[nip][0], b[nip][1], b[nip][2], b[nip][3],
                        boff[nip] + hiB + ks * 32);
            #pragma unroll
            for (int mi = 0; mi < 2; ++mi)
                #pragma unroll
                for (int nip = 0; nip < 4; ++nip) {
                    MMA16816(acc[mi][nip * 2 + 0], a[mi], b[nip][0], b[nip][1]);
                    MMA16816(acc[mi][nip * 2 + 1], a[mi], b[nip][2], b[nip][3]);
                }
            if (doLo) {
                #pragma unroll
                for (int nip = 0; nip < 4; ++nip)
                    LDSM_X4(b[nip][0], b[nip][1], b[nip][2], b[nip][3],
                            boff[nip] + loB + ks * 32);
                #pragma unroll
                for (int mi = 0; mi < 2; ++mi)
                    #pragma unroll
                    for (int nip = 0; nip < 4; ++nip) {
                        MMA16816(acc[mi][nip * 2 + 0], a[mi], b[nip][0], b[nip][1]);
                        MMA16816(acc[mi][nip * 2 + 1], a[mi], b[nip][2], b[nip][3]);
                    }
            }
        }

        if (s < 3) {
            __syncthreads();   // ensure prior-buffer reads done before overwrite? buffers alternate; store to other buffer is safe, but sync orders ldmatrix of cur vs store of next wave reuse
            #pragma unroll
            for (int i = 0; i < 4; ++i) {
                int lin = tid + i * 256;
                int row = lin >> 3, c8 = lin & 7;
                *(uint4*)(As + ((s + 1) & 1) * TILE_B + row * APITCH + c8 * 8) = nxt[i];
            }
        }
        __syncthreads();
    }

    // Epilogue: d2 + best/second-best per point.
    const int r0 = lane >> 2;
    const int c0 = (lane & 3) * 2;
    float bd[4], sd[4]; int bi[4];
    #pragma unroll
    for (int mi = 0; mi < 2; ++mi) {
        #pragma unroll
        for (int h = 0; h < 2; ++h) {
            int qq = mi * 2 + h;
            int pl = wm * 32 + mi * 16 + h * 8 + r0;
            float xq = sxq[pl];
            float b_ = FLT_MAX, s_ = FLT_MAX; int i_ = 0;
            #pragma unroll
            for (int ni = 0; ni < 8; ++ni) {
                #pragma unroll
                for (int u = 0; u < 2; ++u) {
                    int n = wn * 64 + ni * 8 + c0 + u;
                    float d2 = (xq - 2.0f * acc[mi][ni][h * 2 + u]) + scs[n];
                    if (d2 < b_) { s_ = b_; b_ = d2; i_ = n; }
                    else if (d2 < s_) s_ = d2;
                }
            }
            bd[qq] = b_; sd[qq] = s_; bi[qq] = i_;
        }
    }
    #pragma unroll
    for (int off = 1; off <= 2; off <<= 1) {
        #pragma unroll
        for (int qq = 0; qq < 4; ++qq) {
            float obd = __shfl_xor_sync(0xFFFFFFFFu, bd[qq], off);
            int   obi = __shfl_xor_sync(0xFFFFFFFFu, bi[qq], off);
            float osd = __shfl_xor_sync(0xFFFFFFFFu, sd[qq], off);
            bool take = (obd < bd[qq]) || (obd == bd[qq] && obi < bi[qq]);
            float loser = take ? bd[qq] : obd;
            sd[qq] = fminf(fminf(sd[qq], osd), loser);
            if (take) { bd[qq] = obd; bi[qq] = obi; }
        }
    }
    if ((lane & 3) == 0) {
        #pragma unroll
        for (int qq = 0; qq < 4; ++qq) {
            int pl = wm * 32 + (qq >> 1) * 16 + (qq & 1) * 8 + r0;
            redD[pl * 2 + wn] = bd[qq];
            redI[pl * 2 + wn] = bi[qq];
            redS[pl * 2 + wn] = sd[qq];
        }
    }
    __syncthreads();

    if (tid < 128) {
        int p = p0 + tid;
        if (p < m) {
            float b_ = redD[tid * 2], s_ = redS[tid * 2];
            int i_ = redI[tid * 2];
            float od = redD[tid * 2 + 1], os = redS[tid * 2 + 1];
            int oi = redI[tid * 2 + 1];
            bool take = (od < b_) || (od == b_ && oi < i_);
            float loser = take ? b_ : od;
            s_ = fminf(fminf(s_, os), loser);
            if (take) { b_ = od; i_ = oi; }
            g_clusters[p] = i_;
            if (s_ - b_ < TAU) {
                int w = atomicAdd(&g_nflag, 1);
                g_flag[w] = p;
            }
        }
    }
}

// ---------------------------------------------------------------------------
// Stage 2: near-tie refinement in fp64, reference fp32 op order, first-wins.
// ---------------------------------------------------------------------------
__global__ void __launch_bounds__(128)
refine_kernel(const float* __restrict__ X) {
    if (*(volatile int*)&g_done) return;
    int n = *(volatile int*)&g_nflag;
    int c = threadIdx.x;
    __shared__ float sD[128];
    __shared__ int   sI[128];

    for (int w = blockIdx.x; w < n; w += gridDim.x) {
        int p = g_flag[w];
        const float* xr = &X[(size_t)p * NDIM];
        const float* cr = &g_cent[c * NDIM];
        double ac[8] = {0, 0, 0, 0, 0, 0, 0, 0};
        #pragma unroll
        for (int k = 0; k < 16; ++k)
            #pragma unroll
            for (int j = 0; j < 8; ++j)
                ac[j] += (double)xr[k * 8 + j] * (double)cr[k * 8 + j];
        double dot = ((ac[0] + ac[1]) + (ac[2] + ac[3])) +
                     ((ac[4] + ac[5]) + (ac[6] + ac[7]));
        float dotf = (float)dot;
        float t = g_xsq[p] - 2.0f * dotf;
        float d2 = t + g_csqf[c];

        sD[c] = d2; sI[c] = c;
        __syncthreads();
        #pragma unroll
        for (int o = 64; o; o >>= 1) {
            if (c < o) {
                float d = sD[c + o]; int cc = sI[c + o];
                if (d < sD[c] || (d == sD[c] && cc < sI[c])) { sD[c] = d; sI[c] = cc; }
            }
            __syncthreads();
        }
        if (c == 0) g_clusters[p] = sI[0];
        __syncthreads();
    }
}

// ---------------------------------------------------------------------------
// Segment accumulation: 8-way pipelined loads, smem fp64 sums, block partials.
// ---------------------------------------------------------------------------
#define ACCUM_SMEM_BYTES (KCLUST * NDIM * 8 + KCLUST * 4)

__global__ void __launch_bounds__(128)
accum_kernel(const float* __restrict__ X, int m) {
    if (*(volatile int*)&g_done) return;

    extern __shared__ double sm_d[];
    double* ssum = sm_d;
    int*    scnt = (int*)(sm_d + KCLUST * NDIM);

    const int tid = threadIdx.x;
    for (int i = tid; i < KCLUST * NDIM; i += 128) ssum[i] = 0.0;
    scnt[tid] = 0;
    __syncthreads();

    int chunk = (m + NBLK_ACC - 1) / NBLK_ACC;
    int lo = blockIdx.x * chunk;
    int hi = lo + chunk; if (hi > m) hi = m;

    int i = lo;
    for (; i + 8 <= hi; i += 8) {
        int cc[8]; float xv[8];
        #pragma unroll
        for (int j = 0; j < 8; ++j) cc[j] = g_clusters[i + j];
        #pragma unroll
        for (int j = 0; j < 8; ++j) xv[j] = X[(size_t)(i + j) * NDIM + tid];
        if (tid < 8) atomicAdd(&scnt[cc[tid]], 1);
        #pragma unroll
        for (int j = 0; j < 8; ++j)
            ssum[cc[j] * NDIM + tid] += (double)xv[j];
    }
    for (; i < hi; ++i) {
        int c = g_clusters[i];
        float x = X[(size_t)i * NDIM + tid];
        if (tid == 0) atomicAdd(&scnt[c], 1);
        ssum[c * NDIM + tid] += (double)x;
    }
    __syncthreads();

    double* part = g_part[blockIdx.x];
    for (int k = tid; k < KCLUST * NDIM; k += 128) part[k] = ssum[k];
    atomicAdd(&g_counts[tid], scnt[tid]);
}

// ---------------------------------------------------------------------------
__global__ void __launch_bounds__(128)
update_a_kernel(int iter) {
    if (*(volatile int*)&g_done) return;
    int k = blockIdx.x, j = threadIdx.x;
    int idx = k * NDIM + j;

    double ac[8] = {0, 0, 0, 0, 0, 0, 0, 0};
    #pragma unroll 1
    for (int b = 0; b < NBLK_ACC; b += 8)
        #pragma unroll
        for (int u = 0; u < 8; ++u) ac[u] += g_part[b + u][idx];
    double s = ((ac[0] + ac[1]) + (ac[2] + ac[3])) +
               ((ac[4] + ac[5]) + (ac[6] + ac[7]));
    float sf = (float)s;

    int cnt = g_counts[k];
    float old = g_cent[idx];
    float newc = (cnt > 0) ? (sf / fmaxf((float)cnt, 1.0f)) : old;
    g_cent_new[idx] = newc;

    float d = newc - old;
    __shared__ float rb[128];
    rb[j] = d * d;
    __syncthreads();
    #pragma unroll
    for (int o = 64; o; o >>= 1) {
        if (j < o) rb[j] += rb[j + o];
        __syncthreads();
    }
    if (j == 0) {
        if (rb[0] < 1e-8f) atomicAdd(&g_conv[iter], 1);
        g_counts[k] = 0;
        if (k == 0) g_nflag = 0;
    }
}

__global__ void __launch_bounds__(128)
update_b_kernel(int iter) {
    if (*(volatile int*)&g_done) return;
    int k = blockIdx.x, j = threadIdx.x;
    int cv = g_conv[iter];
    if (cv == KCLUST) {
        if (k == 0 && j == 0) g_done = 1;
        return;
    }
    int idx = k * NDIM + j;
    float v = g_cent_new[idx];
    g_cent[idx] = v;
    __nv_bfloat16 hi = __float2bfloat16(v);
    g_chi[idx] = hi;
    g_clo[idx] = __float2bfloat16(v - __bfloat162float(hi));

    __shared__ double rb[128];
    rb[j] = (double)v * (double)v;
    __syncthreads();
    #pragma unroll
    for (int o = 64; o; o >>= 1) {
        if (j < o) rb[j] += rb[j + o];
        __syncthreads();
    }
    if (j == 0) g_csqf[k] = (float)rb[0];
}

// ---------------------------------------------------------------------------
__global__ void finalize_kernel(float* __restrict__ out, int m, int out_size) {
    int idx = blockIdx.x * 256 + threadIdx.x;
    const int nc = KCLUST * NDIM;
    if (out_size >= nc + m) {
        if (idx < nc) out[idx] = g_cent[idx];
        else if (idx < nc + m) out[idx] = (float)g_clusters[idx - nc];
    } else if (out_size == m) {
        if (idx < m) out[idx] = (float)g_clusters[idx];
    } else {
        if (idx < out_size && idx < nc) out[idx] = g_cent[idx];
    }
}

// ---------------------------------------------------------------------------
extern "C" void kernel_launch(void* const* d_in, const int* in_sizes, int n_in,
                              void* d_out, int out_size) {
    const float* X  = (const float*)d_in[0];
    const float* C0 = (const float*)d_in[1];
    int m = in_sizes[0] / NDIM;
    if (m > MAX_M) m = MAX_M;

    cudaFuncSetAttribute(assign_tc_kernel,
                         cudaFuncAttributeMaxDynamicSharedMemorySize,
                         ASSIGN_TC_SMEM);
    cudaFuncSetAttribute(accum_kernel,
                         cudaFuncAttributeMaxDynamicSharedMemorySize,
                         ACCUM_SMEM_BYTES);

    init_kernel<<<129, 128>>>(C0);
    xprep_kernel<<<(MAX_M + 7) / 8, 256>>>(X, m);

    int ablocks = (m + 127) / 128;
    for (int it = 0; it < MAXIT; ++it) {
        assign_tc_kernel<<<ablocks, 256, ASSIGN_TC_SMEM>>>(m);
        refine_kernel<<<256, 128>>>(X);
        accum_kernel<<<NBLK_ACC, 128, ACCUM_SMEM_BYTES>>>(X, m);
        update_a_kernel<<<128, 128>>>(it);
        update_b_kernel<<<128, 128>>>(it);
    }

    int fb = (out_size + 255) / 256;
    if (fb < 1) fb = 1;
    finalize_kernel<<<fb, 256>>>((float*)d_out, m, out_size);
}

// round 5
// speedup vs baseline: 1.3376x; 1.0862x over previous
#include <cuda_runtime.h>
#include <cuda_bf16.h>
#include <cfloat>
#include <cstdint>

// ---------------------------------------------------------------------------
// K-means: X [m,128] fp32, centroids_init [128,128] fp32, K=128, 15 iters,
// tol=1e-4. Assignment via bf16-split tensor-core GEMM (3 logical passes,
// ~2^-17 dot accuracy) with in-block fp64 near-tie refinement replaying the
// reference fp32 op order. Segment sums: fp32 block partials (deterministic),
// fp64 merge.
// ---------------------------------------------------------------------------

#define KCLUST 128
#define NDIM   128
#define MAXIT  15
#define MAX_M  100352
#define NBLK_ACC 128
#define TAU 4e-3f
#define APITCH 72   // bf16 pitch for 64-col smem tiles (conflict-free ldmatrix)

__device__ float  g_cent[KCLUST * NDIM];
__device__ float  g_cent_new[KCLUST * NDIM];
__device__ float  g_csqf[KCLUST];
__device__ float  g_part[NBLK_ACC][KCLUST * NDIM];
__device__ int    g_counts[KCLUST];
__device__ int    g_clusters[MAX_M];
__device__ float  g_xsq[MAX_M];
__device__ int    g_conv[MAXIT + 1];
__device__ int    g_done;

__device__ __nv_bfloat16 g_xhi[MAX_M * NDIM];
__device__ __nv_bfloat16 g_xlo[MAX_M * NDIM];
__device__ __nv_bfloat16 g_chi[KCLUST * NDIM];
__device__ __nv_bfloat16 g_clo[KCLUST * NDIM];

// ---------------------------------------------------------------------------
__global__ void init_kernel(const float* __restrict__ c0) {
    int b = blockIdx.x, t = threadIdx.x;
    if (b < 128) {
        int idx = b * 128 + t;
        float v = c0[idx];
        g_cent[idx] = v;
        __nv_bfloat16 hi = __float2bfloat16(v);
        g_chi[idx] = hi;
        g_clo[idx] = __float2bfloat16(v - __bfloat162float(hi));
        __shared__ double rb[128];
        rb[t] = (double)v * (double)v;
        __syncthreads();
        #pragma unroll
        for (int o = 64; o; o >>= 1) {
            if (t < o) rb[t] += rb[t + o];
            __syncthreads();
        }
        if (t == 0) g_csqf[b] = (float)rb[0];
    } else {
        if (t < KCLUST) g_counts[t] = 0;
        if (t < MAXIT + 1) g_conv[t] = 0;
        if (t == 0) g_done = 0;
    }
}

// ---------------------------------------------------------------------------
// One-time: fused x_sq (fp64->fp32) + bf16 split of X (+ zero padded rows).
// ---------------------------------------------------------------------------
__global__ void __launch_bounds__(256)
xprep_kernel(const float* __restrict__ X, int m) {
    int row = blockIdx.x * 8 + (threadIdx.x >> 5);
    int lane = threadIdx.x & 31;
    if (row >= MAX_M) return;
    __nv_bfloat162* hip = (__nv_bfloat162*)(g_xhi + (size_t)row * NDIM + lane * 4);
    __nv_bfloat162* lop = (__nv_bfloat162*)(g_xlo + (size_t)row * NDIM + lane * 4);
    if (row < m) {
        float4 v = *reinterpret_cast<const float4*>(&X[(size_t)row * NDIM + lane * 4]);
        float f[4] = {v.x, v.y, v.z, v.w};
        __nv_bfloat16 h[4], l[4];
        #pragma unroll
        for (int j = 0; j < 4; ++j) {
            h[j] = __float2bfloat16(f[j]);
            l[j] = __float2bfloat16(f[j] - __bfloat162float(h[j]));
        }
        hip[0] = __nv_bfloat162(h[0], h[1]);
        hip[1] = __nv_bfloat162(h[2], h[3]);
        lop[0] = __nv_bfloat162(l[0], l[1]);
        lop[1] = __nv_bfloat162(l[2], l[3]);
        double s = (double)v.x * v.x + (double)v.y * v.y +
                   (double)v.z * v.z + (double)v.w * v.w;
        #pragma unroll
        for (int o = 16; o; o >>= 1) s += __shfl_xor_sync(0xFFFFFFFFu, s, o);
        if (lane == 0) g_xsq[row] = (float)s;
    } else {
        __nv_bfloat162 z(__float2bfloat16(0.0f), __float2bfloat16(0.0f));
        hip[0] = z; hip[1] = z; lop[0] = z; lop[1] = z;
    }
}

// ---------------------------------------------------------------------------
// Assignment: bf16-split tensor-core GEMM + argmin + fused in-block fp64
// refinement of near-ties (replays reference fp32 op order, first-index-wins).
// ---------------------------------------------------------------------------
#define LDSM_X4(r0, r1, r2, r3, addr) \
    asm volatile("ldmatrix.sync.aligned.m8n8.x4.shared.b16 {%0,%1,%2,%3}, [%4];" \
        : "=r"(r0), "=r"(r1), "=r"(r2), "=r"(r3) : "r"(addr))

#define MMA16816(d, a, b0, b1) \
    asm volatile("mma.sync.aligned.m16n8k16.row.col.f32.bf16.bf16.f32 " \
        "{%0,%1,%2,%3},{%4,%5,%6,%7},{%8,%9},{%0,%1,%2,%3};" \
        : "+f"(d[0]), "+f"(d[1]), "+f"(d[2]), "+f"(d[3]) \
        : "r"(a[0]), "r"(a[1]), "r"(a[2]), "r"(a[3]), "r"(b0), "r"(b1))

#define TILE_B (128 * APITCH)
#define ASSIGN_TC_SMEM ((4 + 2) * TILE_B * 2 + 1024)

__global__ void __launch_bounds__(256, 2)
assign_tc_kernel(const float* __restrict__ X, int m) {
    if (*(volatile int*)&g_done) return;

    extern __shared__ char sm8[];
    __nv_bfloat16* Cs = (__nv_bfloat16*)sm8;         // 4 centroid chunks
    __nv_bfloat16* As = Cs + 4 * TILE_B;             // 2 A buffers
    float* scs = (float*)(As + 2 * TILE_B);
    float* sxq = scs + 128;
    // epilogue scratch (overlays Cs after final sync)
    float* redD = (float*)sm8;
    int*   redI = (int*)(sm8 + 2048);
    float* redS = (float*)(sm8 + 4096);

    __shared__ int   s_nf;
    __shared__ int   s_fl[128];
    __shared__ float sD[128];
    __shared__ int   sI[128];

    const int tid = threadIdx.x;
    const int lane = tid & 31;
    const int wid = tid >> 5;
    const int wm = wid & 3;       // M tile (32 rows)
    const int wn = wid >> 2;      // N tile (64 cols)
    const int p0 = blockIdx.x * 128;

    if (tid == 0) s_nf = 0;
    if (tid < 128) {
        scs[tid] = g_csqf[tid];
        int p = p0 + tid;
        sxq[tid] = (p < m) ? g_xsq[p] : 0.0f;
    }

    // Load all 4 centroid chunks: {chi kc0, chi kc64, clo kc0, clo kc64}.
    #pragma unroll
    for (int ch = 0; ch < 4; ++ch) {
        const __nv_bfloat16* Bp = (ch < 2) ? g_chi : g_clo;
        int kc = (ch & 1) * 64;
        #pragma unroll
        for (int i = 0; i < 4; ++i) {
            int lin = tid + i * 256;
            int row = lin >> 3, c8 = lin & 7;
            uint4 vb = *(const uint4*)(Bp + row * 128 + kc + c8 * 8);
            *(uint4*)(Cs + ch * TILE_B + row * APITCH + c8 * 8) = vb;
        }
    }

    // Prefetch + stage A stage 0 (xhi, kc0).
    uint4 nxt[4];
    {
        #pragma unroll
        for (int i = 0; i < 4; ++i) {
            int lin = tid + i * 256;
            int row = lin >> 3, c8 = lin & 7;
            nxt[i] = *(const uint4*)(g_xhi + (size_t)(p0 + row) * 128 + c8 * 8);
        }
        #pragma unroll
        for (int i = 0; i < 4; ++i) {
            int lin = tid + i * 256;
            int row = lin >> 3, c8 = lin & 7;
            *(uint4*)(As + row * APITCH + c8 * 8) = nxt[i];
        }
    }
    __syncthreads();

    const int q = lane >> 3;
    const int r = lane & 7;
    uint32_t asBase = (uint32_t)__cvta_generic_to_shared(As);
    uint32_t csBase = (uint32_t)__cvta_generic_to_shared(Cs);
    uint32_t aoff[2];
    #pragma unroll
    for (int mi = 0; mi < 2; ++mi)
        aoff[mi] = asBase +
            (uint32_t)(((wm * 32 + mi * 16 + (q & 1) * 8 + r) * APITCH + (q >> 1) * 8) * 2);
    uint32_t boff[4];
    #pragma unroll
    for (int nip = 0; nip < 4; ++nip)
        boff[nip] = csBase +
            (uint32_t)(((wn * 64 + nip * 16 + (q >> 1) * 8 + r) * APITCH + (q & 1) * 8) * 2);

    float acc[2][8][4];
    #pragma unroll
    for (int mi = 0; mi < 2; ++mi)
        #pragma unroll
        for (int ni = 0; ni < 8; ++ni)
            #pragma unroll
            for (int u = 0; u < 4; ++u) acc[mi][ni][u] = 0.0f;

    const uint32_t TILE_BYTES = TILE_B * 2;

    // Stages: s0: xhi kc0 x {Chi0,Clo0}  s1: xhi kc64 x {Chi1,Clo1}
    //         s2: xlo kc0 x Chi0         s3: xlo kc64 x Chi1
    #pragma unroll 1
    for (int s = 0; s < 4; ++s) {
        if (s < 3) {
            const __nv_bfloat16* Ap = (s + 1 < 2) ? g_xhi : g_xlo;
            int kc = ((s + 1) & 1) * 64;
            #pragma unroll
            for (int i = 0; i < 4; ++i) {
                int lin = tid + i * 256;
                int row = lin >> 3, c8 = lin & 7;
                nxt[i] = *(const uint4*)(Ap + (size_t)(p0 + row) * 128 + kc + c8 * 8);
            }
        }

        const uint32_t abuf = (uint32_t)(s & 1) * TILE_BYTES;
        const uint32_t hiB = (uint32_t)(s & 1) * TILE_BYTES;
        const uint32_t loB = (uint32_t)(2 + (s & 1)) * TILE_BYTES;
        const bool doLo = (s < 2);

        #pragma unroll
        for (int ks = 0; ks < 4; ++ks) {
            uint32_t a[2][4];
            #pragma unroll
            for (int mi = 0; mi < 2; ++mi)
                LDSM_X4(a[mi][0], a[mi][1], a[mi][2], a[mi][3],
                        aoff[mi] + abuf + ks * 32);
            uint32_t b[4][4];
            #pragma unroll
            for (int nip = 0; nip < 4; ++nip)
                LDSM_X4(b[nip][0], b[nip][1], b[nip][2], b[nip][3],
                        boff[nip] + hiB + ks * 32);
            #pragma unroll
            for (int mi = 0; mi < 2; ++mi)
                #pragma unroll
                for (int nip = 0; nip < 4; ++nip) {
                    MMA16816(acc[mi][nip * 2 + 0], a[mi], b[nip][0], b[nip][1]);
                    MMA16816(acc[mi][nip * 2 + 1], a[mi], b[nip][2], b[nip][3]);
                }
            if (doLo) {
                #pragma unroll
                for (int nip = 0; nip < 4; ++nip)
                    LDSM_X4(b[nip][0], b[nip][1], b[nip][2], b[nip][3],
                            boff[nip] + loB + ks * 32);
                #pragma unroll
                for (int mi = 0; mi < 2; ++mi)
                    #pragma unroll
                    for (int nip = 0; nip < 4; ++nip) {
                        MMA16816(acc[mi][nip * 2 + 0], a[mi], b[nip][0], b[nip][1]);
                        MMA16816(acc[mi][nip * 2 + 1], a[mi], b[nip][2], b[nip][3]);
                    }
            }
        }

        if (s < 3) {
            // buffers alternate; prior reads of the target buffer finished at
            // the end-of-stage sync of s-1, so store directly then sync once.
            #pragma unroll
            for (int i = 0; i < 4; ++i) {
                int lin = tid + i * 256;
                int row = lin >> 3, c8 = lin & 7;
                *(uint4*)(As + ((s + 1) & 1) * TILE_B + row * APITCH + c8 * 8) = nxt[i];
            }
        }
        __syncthreads();
    }

    // Epilogue: d2 + best/second-best per point.
    const int r0 = lane >> 2;
    const int c0 = (lane & 3) * 2;
    float bd[4], sd[4]; int bi[4];
    #pragma unroll
    for (int mi = 0; mi < 2; ++mi) {
        #pragma unroll
        for (int h = 0; h < 2; ++h) {
            int qq = mi * 2 + h;
            int pl = wm * 32 + mi * 16 + h * 8 + r0;
            float xq = sxq[pl];
            float b_ = FLT_MAX, s_ = FLT_MAX; int i_ = 0;
            #pragma unroll
            for (int ni = 0; ni < 8; ++ni) {
                #pragma unroll
                for (int u = 0; u < 2; ++u) {
                    int n = wn * 64 + ni * 8 + c0 + u;
                    float d2 = (xq - 2.0f * acc[mi][ni][h * 2 + u]) + scs[n];
                    if (d2 < b_) { s_ = b_; b_ = d2; i_ = n; }
                    else if (d2 < s_) s_ = d2;
                }
            }
            bd[qq] = b_; sd[qq] = s_; bi[qq] = i_;
        }
    }
    #pragma unroll
    for (int off = 1; off <= 2; off <<= 1) {
        #pragma unroll
        for (int qq = 0; qq < 4; ++qq) {
            float obd = __shfl_xor_sync(0xFFFFFFFFu, bd[qq], off);
            int   obi = __shfl_xor_sync(0xFFFFFFFFu, bi[qq], off);
            float osd = __shfl_xor_sync(0xFFFFFFFFu, sd[qq], off);
            bool take = (obd < bd[qq]) || (obd == bd[qq] && obi < bi[qq]);
            float loser = take ? bd[qq] : obd;
            sd[qq] = fminf(fminf(sd[qq], osd), loser);
            if (take) { bd[qq] = obd; bi[qq] = obi; }
        }
    }
    if ((lane & 3) == 0) {
        #pragma unroll
        for (int qq = 0; qq < 4; ++qq) {
            int pl = wm * 32 + (qq >> 1) * 16 + (qq & 1) * 8 + r0;
            redD[pl * 2 + wn] = bd[qq];
            redI[pl * 2 + wn] = bi[qq];
            redS[pl * 2 + wn] = sd[qq];
        }
    }
    __syncthreads();

    if (tid < 128) {
        int p = p0 + tid;
        if (p < m) {
            float b_ = redD[tid * 2], s_ = redS[tid * 2];
            int i_ = redI[tid * 2];
            float od = redD[tid * 2 + 1], os = redS[tid * 2 + 1];
            int oi = redI[tid * 2 + 1];
            bool take = (od < b_) || (od == b_ && oi < i_);
            float loser = take ? b_ : od;
            s_ = fminf(fminf(s_, os), loser);
            if (take) { b_ = od; i_ = oi; }
            g_clusters[p] = i_;
            if (s_ - b_ < TAU) {
                int w = atomicAdd(&s_nf, 1);
                s_fl[w] = tid;
            }
        }
    }
    __syncthreads();

    // Fused near-tie refinement: fp64 dot vs all 128 centroids, then the
    // reference's fp32 op sequence, first-index-wins argmin.
    int nf = s_nf;
    for (int f = 0; f < nf; ++f) {
        int pl = s_fl[f];
        int p = p0 + pl;
        if (tid < 128) {
            const float* xr = X + (size_t)p * NDIM;
            const float* cr = g_cent + tid * NDIM;
            double ac[8] = {0, 0, 0, 0, 0, 0, 0, 0};
            #pragma unroll
            for (int k = 0; k < 16; ++k)
                #pragma unroll
                for (int j = 0; j < 8; ++j)
                    ac[j] += (double)xr[k * 8 + j] * (double)cr[k * 8 + j];
            double dot = ((ac[0] + ac[1]) + (ac[2] + ac[3])) +
                         ((ac[4] + ac[5]) + (ac[6] + ac[7]));
            float dotf = (float)dot;
            float t = sxq[pl] - 2.0f * dotf;
            float d2 = t + scs[tid];
            sD[tid] = d2; sI[tid] = tid;
        }
        __syncthreads();
        #pragma unroll
        for (int o = 64; o; o >>= 1) {
            if (tid < o) {
                float d = sD[tid + o]; int cc = sI[tid + o];
                if (d < sD[tid] || (d == sD[tid] && cc < sI[tid])) {
                    sD[tid] = d; sI[tid] = cc;
                }
            }
            __syncthreads();
        }
        if (tid == 0) g_clusters[p] = sI[0];
        __syncthreads();
    }
}

// ---------------------------------------------------------------------------
// Segment accumulation: 8-way pipelined loads, fp32 smem sums (deterministic
// fixed order), fp32 block partials + integer counts.
// ---------------------------------------------------------------------------
#define ACCUM_SMEM_BYTES (KCLUST * NDIM * 4 + KCLUST * 4)

__global__ void __launch_bounds__(128)
accum_kernel(const float* __restrict__ X, int m) {
    if (*(volatile int*)&g_done) return;

    extern __shared__ float sm_f[];
    float* ssum = sm_f;
    int*   scnt = (int*)(sm_f + KCLUST * NDIM);

    const int tid = threadIdx.x;
    for (int i = tid; i < KCLUST * NDIM; i += 128) ssum[i] = 0.0f;
    scnt[tid] = 0;
    __syncthreads();

    int chunk = (m + NBLK_ACC - 1) / NBLK_ACC;
    int lo = blockIdx.x * chunk;
    int hi = lo + chunk; if (hi > m) hi = m;

    int i = lo;
    for (; i + 8 <= hi; i += 8) {
        int cc[8]; float xv[8];
        #pragma unroll
        for (int j = 0; j < 8; ++j) cc[j] = g_clusters[i + j];
        #pragma unroll
        for (int j = 0; j < 8; ++j) xv[j] = X[(size_t)(i + j) * NDIM + tid];
        if (tid < 8) atomicAdd(&scnt[cc[tid]], 1);
        #pragma unroll
        for (int j = 0; j < 8; ++j)
            ssum[cc[j] * NDIM + tid] += xv[j];
    }
    for (; i < hi; ++i) {
        int c = g_clusters[i];
        float x = X[(size_t)i * NDIM + tid];
        if (tid == 0) atomicAdd(&scnt[c], 1);
        ssum[c * NDIM + tid] += x;
    }
    __syncthreads();

    float* part = g_part[blockIdx.x];
    for (int k = tid; k < KCLUST * NDIM; k += 128) part[k] = ssum[k];
    atomicAdd(&g_counts[tid], scnt[tid]);
}

// ---------------------------------------------------------------------------
__global__ void __launch_bounds__(128)
update_a_kernel(int iter) {
    if (*(volatile int*)&g_done) return;
    int k = blockIdx.x, j = threadIdx.x;
    int idx = k * NDIM + j;

    double ac[8] = {0, 0, 0, 0, 0, 0, 0, 0};
    #pragma unroll 1
    for (int b = 0; b < NBLK_ACC; b += 8)
        #pragma unroll
        for (int u = 0; u < 8; ++u) ac[u] += (double)g_part[b + u][idx];
    double s = ((ac[0] + ac[1]) + (ac[2] + ac[3])) +
               ((ac[4] + ac[5]) + (ac[6] + ac[7]));
    float sf = (float)s;

    int cnt = g_counts[k];
    float old = g_cent[idx];
    float newc = (cnt > 0) ? (sf / fmaxf((float)cnt, 1.0f)) : old;
    g_cent_new[idx] = newc;

    float d = newc - old;
    __shared__ float rb[128];
    rb[j] = d * d;
    __syncthreads();
    #pragma unroll
    for (int o = 64; o; o >>= 1) {
        if (j < o) rb[j] += rb[j + o];
        __syncthreads();
    }
    if (j == 0) {
        if (rb[0] < 1e-8f) atomicAdd(&g_conv[iter], 1);
        g_counts[k] = 0;
    }
}

__global__ void __launch_bounds__(128)
update_b_kernel(int iter) {
    if (*(volatile int*)&g_done) return;
    int k = blockIdx.x, j = threadIdx.x;
    int cv = g_conv[iter];
    if (cv == KCLUST) {
        if (k == 0 && j == 0) g_done = 1;
        return;
    }
    int idx = k * NDIM + j;
    float v = g_cent_new[idx];
    g_cent[idx] = v;
    __nv_bfloat16 hi = __float2bfloat16(v);
    g_chi[idx] = hi;
    g_clo[idx] = __float2bfloat16(v - __bfloat162float(hi));

    __shared__ double rb[128];
    rb[j] = (double)v * (double)v;
    __syncthreads();
    #pragma unroll
    for (int o = 64; o; o >>= 1) {
        if (j < o) rb[j] += rb[j + o];
        __syncthreads();
    }
    if (j == 0) g_csqf[k] = (float)rb[0];
}

// ---------------------------------------------------------------------------
__global__ void finalize_kernel(float* __restrict__ out, int m, int out_size) {
    int idx = blockIdx.x * 256 + threadIdx.x;
    const int nc = KCLUST * NDIM;
    if (out_size >= nc + m) {
        if (idx < nc) out[idx] = g_cent[idx];
        else if (idx < nc + m) out[idx] = (float)g_clusters[idx - nc];
    } else if (out_size == m) {
        if (idx < m) out[idx] = (float)g_clusters[idx];
    } else {
        if (idx < out_size && idx < nc) out[idx] = g_cent[idx];
    }
}

// ---------------------------------------------------------------------------
extern "C" void kernel_launch(void* const* d_in, const int* in_sizes, int n_in,
                              void* d_out, int out_size) {
    const float* X  = (const float*)d_in[0];
    const float* C0 = (const float*)d_in[1];
    int m = in_sizes[0] / NDIM;
    if (m > MAX_M) m = MAX_M;

    cudaFuncSetAttribute(assign_tc_kernel,
                         cudaFuncAttributeMaxDynamicSharedMemorySize,
                         ASSIGN_TC_SMEM);
    cudaFuncSetAttribute(accum_kernel,
                         cudaFuncAttributeMaxDynamicSharedMemorySize,
                         ACCUM_SMEM_BYTES);

    init_kernel<<<129, 128>>>(C0);
    xprep_kernel<<<(MAX_M + 7) / 8, 256>>>(X, m);

    int ablocks = (m + 127) / 128;
    for (int it = 0; it < MAXIT; ++it) {
        assign_tc_kernel<<<ablocks, 256, ASSIGN_TC_SMEM>>>(X, m);
        accum_kernel<<<NBLK_ACC, 128, ACCUM_SMEM_BYTES>>>(X, m);
        update_a_kernel<<<128, 128>>>(it);
        update_b_kernel<<<128, 128>>>(it);
    }

    int fb = (out_size + 255) / 256;
    if (fb < 1) fb = 1;
    finalize_kernel<<<fb, 256>>>((float*)d_out, m, out_size);
}

// round 7
// speedup vs baseline: 1.3389x; 1.0009x over previous
#include <cuda_runtime.h>
#include <cuda_bf16.h>
#include <cfloat>
#include <cstdint>

// ---------------------------------------------------------------------------
// K-means: X [m,128] fp32, centroids_init [128,128] fp32, K=128, 15 iters,
// tol=1e-4. Assignment via bf16-split tensor-core GEMM (3 logical passes)
// with in-block fp64 near-tie refinement. Segment sums read EXACT fp32 X
// (required: centroid error must stay ~1e-8 or assignment flips amplify),
// fp32 block partials in smem (2 independent groups), fp64 merge.
// ---------------------------------------------------------------------------

#define KCLUST 128
#define NDIM   128
#define MAXIT  15
#define MAX_M  100352
#define NBLK_ACC 148
#define TAU 4e-3f
#define APITCH 72   // bf16 pitch for 64-col smem tiles (conflict-free ldmatrix)

__device__ float  g_cent[KCLUST * NDIM];
__device__ float  g_cent_new[KCLUST * NDIM];
__device__ float  g_csqf[KCLUST];
__device__ float  g_part[NBLK_ACC][KCLUST * NDIM];
__device__ int    g_counts[KCLUST];
__device__ int    g_clusters[MAX_M];
__device__ float  g_xsq[MAX_M];
__device__ int    g_conv[MAXIT + 1];
__device__ int    g_done;

__device__ __nv_bfloat16 g_xhi[MAX_M * NDIM];
__device__ __nv_bfloat16 g_xlo[MAX_M * NDIM];
__device__ __nv_bfloat16 g_chi[KCLUST * NDIM];
__device__ __nv_bfloat16 g_clo[KCLUST * NDIM];

// ---------------------------------------------------------------------------
__global__ void init_kernel(const float* __restrict__ c0) {
    int b = blockIdx.x, t = threadIdx.x;
    if (b < 128) {
        int idx = b * 128 + t;
        float v = c0[idx];
        g_cent[idx] = v;
        __nv_bfloat16 hi = __float2bfloat16(v);
        g_chi[idx] = hi;
        g_clo[idx] = __float2bfloat16(v - __bfloat162float(hi));
        __shared__ double rb[128];
        rb[t] = (double)v * (double)v;
        __syncthreads();
        #pragma unroll
        for (int o = 64; o; o >>= 1) {
            if (t < o) rb[t] += rb[t + o];
            __syncthreads();
        }
        if (t == 0) g_csqf[b] = (float)rb[0];
    } else {
        if (t < KCLUST) g_counts[t] = 0;
        if (t < MAXIT + 1) g_conv[t] = 0;
        if (t == 0) g_done = 0;
    }
}

// ---------------------------------------------------------------------------
// One-time: fused x_sq (fp64->fp32) + bf16 split of X (+ zero padded rows).
// ---------------------------------------------------------------------------
__global__ void __launch_bounds__(256)
xprep_kernel(const float* __restrict__ X, int m) {
    int row = blockIdx.x * 8 + (threadIdx.x >> 5);
    int lane = threadIdx.x & 31;
    if (row >= MAX_M) return;
    __nv_bfloat162* hip = (__nv_bfloat162*)(g_xhi + (size_t)row * NDIM + lane * 4);
    __nv_bfloat162* lop = (__nv_bfloat162*)(g_xlo + (size_t)row * NDIM + lane * 4);
    if (row < m) {
        float4 v = *reinterpret_cast<const float4*>(&X[(size_t)row * NDIM + lane * 4]);
        float f[4] = {v.x, v.y, v.z, v.w};
        __nv_bfloat16 h[4], l[4];
        #pragma unroll
        for (int j = 0; j < 4; ++j) {
            h[j] = __float2bfloat16(f[j]);
            l[j] = __float2bfloat16(f[j] - __bfloat162float(h[j]));
        }
        hip[0] = __nv_bfloat162(h[0], h[1]);
        hip[1] = __nv_bfloat162(h[2], h[3]);
        lop[0] = __nv_bfloat162(l[0], l[1]);
        lop[1] = __nv_bfloat162(l[2], l[3]);
        double s = (double)v.x * v.x + (double)v.y * v.y +
                   (double)v.z * v.z + (double)v.w * v.w;
        #pragma unroll
        for (int o = 16; o; o >>= 1) s += __shfl_xor_sync(0xFFFFFFFFu, s, o);
        if (lane == 0) g_xsq[row] = (float)s;
    } else {
        __nv_bfloat162 z(__float2bfloat16(0.0f), __float2bfloat16(0.0f));
        hip[0] = z; hip[1] = z; lop[0] = z; lop[1] = z;
    }
}

// ---------------------------------------------------------------------------
// Assignment: bf16-split tensor-core GEMM + argmin + fused in-block fp64
// refinement of near-ties (replays reference fp32 op order, first-index-wins).
// ---------------------------------------------------------------------------
#define LDSM_X4(r0, r1, r2, r3, addr) \
    asm volatile("ldmatrix.sync.aligned.m8n8.x4.shared.b16 {%0,%1,%2,%3}, [%4];" \
        : "=r"(r0), "=r"(r1), "=r"(r2), "=r"(r3) : "r"(addr))

#define MMA16816(d, a, b0, b1) \
    asm volatile("mma.sync.aligned.m16n8k16.row.col.f32.bf16.bf16.f32 " \
        "{%0,%1,%2,%3},{%4,%5,%6,%7},{%8,%9},{%0,%1,%2,%3};" \
        : "+f"(d[0]), "+f"(d[1]), "+f"(d[2]), "+f"(d[3]) \
        : "r"(a[0]), "r"(a[1]), "r"(a[2]), "r"(a[3]), "r"(b0), "r"(b1))

#define TILE_B (128 * APITCH)
#define ASSIGN_TC_SMEM ((4 + 2) * TILE_B * 2 + 1024)

__global__ void __launch_bounds__(256, 2)
assign_tc_kernel(const float* __restrict__ X, int m) {
    if (*(volatile int*)&g_done) return;

    extern __shared__ char sm8[];
    __nv_bfloat16* Cs = (__nv_bfloat16*)sm8;         // 4 centroid chunks
    __nv_bfloat16* As = Cs + 4 * TILE_B;             // 2 A buffers
    float* scs = (float*)(As + 2 * TILE_B);
    float* sxq = scs + 128;
    float* redD = (float*)sm8;                       // overlays Cs post-GEMM
    int*   redI = (int*)(sm8 + 2048);
    float* redS = (float*)(sm8 + 4096);

    __shared__ int   s_nf;
    __shared__ int   s_fl[128];
    __shared__ float sD[128];
    __shared__ int   sI[128];

    const int tid = threadIdx.x;
    const int lane = tid & 31;
    const int wid = tid >> 5;
    const int wm = wid & 3;
    const int wn = wid >> 2;
    const int p0 = blockIdx.x * 128;

    if (tid == 0) s_nf = 0;
    if (tid < 128) {
        scs[tid] = g_csqf[tid];
        int p = p0 + tid;
        sxq[tid] = (p < m) ? g_xsq[p] : 0.0f;
    }

    #pragma unroll
    for (int ch = 0; ch < 4; ++ch) {
        const __nv_bfloat16* Bp = (ch < 2) ? g_chi : g_clo;
        int kc = (ch & 1) * 64;
        #pragma unroll
        for (int i = 0; i < 4; ++i) {
            int lin = tid + i * 256;
            int row = lin >> 3, c8 = lin & 7;
            uint4 vb = *(const uint4*)(Bp + row * 128 + kc + c8 * 8);
            *(uint4*)(Cs + ch * TILE_B + row * APITCH + c8 * 8) = vb;
        }
    }

    uint4 nxt[4];
    {
        #pragma unroll
        for (int i = 0; i < 4; ++i) {
            int lin = tid + i * 256;
            int row = lin >> 3, c8 = lin & 7;
            nxt[i] = *(const uint4*)(g_xhi + (size_t)(p0 + row) * 128 + c8 * 8);
        }
        #pragma unroll
        for (int i = 0; i < 4; ++i) {
            int lin = tid + i * 256;
            int row = lin >> 3, c8 = lin & 7;
            *(uint4*)(As + row * APITCH + c8 * 8) = nxt[i];
        }
    }
    __syncthreads();

    const int q = lane >> 3;
    const int r = lane & 7;
    uint32_t asBase = (uint32_t)__cvta_generic_to_shared(As);
    uint32_t csBase = (uint32_t)__cvta_generic_to_shared(Cs);
    uint32_t aoff[2];
    #pragma unroll
    for (int mi = 0; mi < 2; ++mi)
        aoff[mi] = asBase +
            (uint32_t)(((wm * 32 + mi * 16 + (q & 1) * 8 + r) * APITCH + (q >> 1) * 8) * 2);
    uint32_t boff[4];
    #pragma unroll
    for (int nip = 0; nip < 4; ++nip)
        boff[nip] = csBase +
            (uint32_t)(((wn * 64 + nip * 16 + (q >> 1) * 8 + r) * APITCH + (q & 1) * 8) * 2);

    float acc[2][8][4];
    #pragma unroll
    for (int mi = 0; mi < 2; ++mi)
        #pragma unroll
        for (int ni = 0; ni < 8; ++ni)
            #pragma unroll
            for (int u = 0; u < 4; ++u) acc[mi][ni][u] = 0.0f;

    const uint32_t TILE_BYTES = TILE_B * 2;

    #pragma unroll 1
    for (int s = 0; s < 4; ++s) {
        if (s < 3) {
            const __nv_bfloat16* Ap = (s + 1 < 2) ? g_xhi : g_xlo;
            int kc = ((s + 1) & 1) * 64;
            #pragma unroll
            for (int i = 0; i < 4; ++i) {
                int lin = tid + i * 256;
                int row = lin >> 3, c8 = lin & 7;
                nxt[i] = *(const uint4*)(Ap + (size_t)(p0 + row) * 128 + kc + c8 * 8);
            }
        }

        const uint32_t abuf = (uint32_t)(s & 1) * TILE_BYTES;
        const uint32_t hiB = (uint32_t)(s & 1) * TILE_BYTES;
        const uint32_t loB = (uint32_t)(2 + (s & 1)) * TILE_BYTES;
        const bool doLo = (s < 2);

        #pragma unroll
        for (int ks = 0; ks < 4; ++ks) {
            uint32_t a[2][4];
            #pragma unroll
            for (int mi = 0; mi < 2; ++mi)
                LDSM_X4(a[mi][0], a[mi][1], a[mi][2], a[mi][3],
                        aoff[mi] + abuf + ks * 32);
            uint32_t b[4][4];
            #pragma unroll
            for (int nip = 0; nip < 4; ++nip)
                LDSM_X4(b[nip][0], b[nip][1], b[nip][2], b[nip][3],
                        boff[nip] + hiB + ks * 32);
            #pragma unroll
            for (int mi = 0; mi < 2; ++mi)
                #pragma unroll
                for (int nip = 0; nip < 4; ++nip) {
                    MMA16816(acc[mi][nip * 2 + 0], a[mi], b[nip][0], b[nip][1]);
                    MMA16816(acc[mi][nip * 2 + 1], a[mi], b[nip][2], b[nip][3]);
                }
            if (doLo) {
                #pragma unroll
                for (int nip = 0; nip < 4; ++nip)
                    LDSM_X4(b[nip][0], b[nip][1], b[nip][2], b[nip][3],
                            boff[nip] + loB + ks * 32);
                #pragma unroll
                for (int mi = 0; mi < 2; ++mi)
                    #pragma unroll
                    for (int nip = 0; nip < 4; ++nip) {
                        MMA16816(acc[mi][nip * 2 + 0], a[mi], b[nip][0], b[nip][1]);
                        MMA16816(acc[mi][nip * 2 + 1], a[mi], b[nip][2], b[nip][3]);
                    }
            }
        }

        if (s < 3) {
            #pragma unroll
            for (int i = 0; i < 4; ++i) {
                int lin = tid + i * 256;
                int row = lin >> 3, c8 = lin & 7;
                *(uint4*)(As + ((s + 1) & 1) * TILE_B + row * APITCH + c8 * 8) = nxt[i];
            }
        }
        __syncthreads();
    }

    const int r0 = lane >> 2;
    const int c0 = (lane & 3) * 2;
    float bd[4], sd[4]; int bi[4];
    #pragma unroll
    for (int mi = 0; mi < 2; ++mi) {
        #pragma unroll
        for (int h = 0; h < 2; ++h) {
            int qq = mi * 2 + h;
            int pl = wm * 32 + mi * 16 + h * 8 + r0;
            float xq = sxq[pl];
            float b_ = FLT_MAX, s_ = FLT_MAX; int i_ = 0;
            #pragma unroll
            for (int ni = 0; ni < 8; ++ni) {
                #pragma unroll
                for (int u = 0; u < 2; ++u) {
                    int n = wn * 64 + ni * 8 + c0 + u;
                    float d2 = (xq - 2.0f * acc[mi][ni][h * 2 + u]) + scs[n];
                    if (d2 < b_) { s_ = b_; b_ = d2; i_ = n; }
                    else if (d2 < s_) s_ = d2;
                }
            }
            bd[qq] = b_; sd[qq] = s_; bi[qq] = i_;
        }
    }
    #pragma unroll
    for (int off = 1; off <= 2; off <<= 1) {
        #pragma unroll
        for (int qq = 0; qq < 4; ++qq) {
            float obd = __shfl_xor_sync(0xFFFFFFFFu, bd[qq], off);
            int   obi = __shfl_xor_sync(0xFFFFFFFFu, bi[qq], off);
            float osd = __shfl_xor_sync(0xFFFFFFFFu, sd[qq], off);
            bool take = (obd < bd[qq]) || (obd == bd[qq] && obi < bi[qq]);
            float loser = take ? bd[qq] : obd;
            sd[qq] = fminf(fminf(sd[qq], osd), loser);
            if (take) { bd[qq] = obd; bi[qq] = obi; }
        }
    }
    if ((lane & 3) == 0) {
        #pragma unroll
        for (int qq = 0; qq < 4; ++qq) {
            int pl = wm * 32 + (qq >> 1) * 16 + (qq & 1) * 8 + r0;
            redD[pl * 2 + wn] = bd[qq];
            redI[pl * 2 + wn] = bi[qq];
            redS[pl * 2 + wn] = sd[qq];
        }
    }
    __syncthreads();

    if (tid < 128) {
        int p = p0 + tid;
        if (p < m) {
            float b_ = redD[tid * 2], s_ = redS[tid * 2];
            int i_ = redI[tid * 2];
            float od = redD[tid * 2 + 1], os = redS[tid * 2 + 1];
            int oi = redI[tid * 2 + 1];
            bool take = (od < b_) || (od == b_ && oi < i_);
            float loser = take ? b_ : od;
            s_ = fminf(fminf(s_, os), loser);
            if (take) { b_ = od; i_ = oi; }
            g_clusters[p] = i_;
            if (s_ - b_ < TAU) {
                int w = atomicAdd(&s_nf, 1);
                s_fl[w] = tid;
            }
        }
    }
    __syncthreads();

    int nf = s_nf;
    for (int f = 0; f < nf; ++f) {
        int pl = s_fl[f];
        int p = p0 + pl;
        if (tid < 128) {
            const float* xr = X + (size_t)p * NDIM;
            const float* cr = g_cent + tid * NDIM;
            double ac[8] = {0, 0, 0, 0, 0, 0, 0, 0};
            #pragma unroll
            for (int k = 0; k < 16; ++k)
                #pragma unroll
                for (int j = 0; j < 8; ++j)
                    ac[j] += (double)xr[k * 8 + j] * (double)cr[k * 8 + j];
            double dot = ((ac[0] + ac[1]) + (ac[2] + ac[3])) +
                         ((ac[4] + ac[5]) + (ac[6] + ac[7]));
            float dotf = (float)dot;
            float t = sxq[pl] - 2.0f * dotf;
            float d2 = t + scs[tid];
            sD[tid] = d2; sI[tid] = tid;
        }
        __syncthreads();
        #pragma unroll
        for (int o = 64; o; o >>= 1) {
            if (tid < o) {
                float d = sD[tid + o]; int cc = sI[tid + o];
                if (d < sD[tid] || (d == sD[tid] && cc < sI[tid])) {
                    sD[tid] = d; sI[tid] = cc;
                }
            }
            __syncthreads();
        }
        if (tid == 0) g_clusters[p] = sI[0];
        __syncthreads();
    }
}

// ---------------------------------------------------------------------------
// Segment accumulation: EXACT fp32 X reads, two private smem accumulator
// groups (race-free +=), 16-point batches for MLP, fp32 block partials.
// ---------------------------------------------------------------------------
#define ACCUM_SMEM_BYTES (2 * KCLUST * NDIM * 4 + 2 * KCLUST * 4)

__global__ void __launch_bounds__(256)
accum_kernel(const float* __restrict__ X, int m) {
    if (*(volatile int*)&g_done) return;

    extern __shared__ float sm_f[];                 // 2 x 16384 floats
    int* scnt = (int*)(sm_f + 2 * KCLUST * NDIM);   // 2 x 128 ints

    const int tid = threadIdx.x;
    const int grp = tid >> 7;          // 0 / 1
    const int dim = tid & 127;
    float* ssum = sm_f + grp * (KCLUST * NDIM);
    int* mycnt = scnt + grp * 128;

    for (int i = tid; i < 2 * KCLUST * NDIM; i += 256) sm_f[i] = 0.0f;
    scnt[tid] = 0;
    __syncthreads();

    int chunk = (m + NBLK_ACC - 1) / NBLK_ACC;
    int lo = blockIdx.x * chunk;
    int hi = lo + chunk; if (hi > m) hi = m;

    int i = lo + grp;
    for (; i + 30 < hi; i += 32) {      // 16 points per group, stride 2
        int cc[16]; float xv[16];
        #pragma unroll
        for (int j = 0; j < 16; ++j) cc[j] = g_clusters[i + 2 * j];
        #pragma unroll
        for (int j = 0; j < 16; ++j)
            xv[j] = X[(size_t)(i + 2 * j) * NDIM + dim];
        if (dim == 0) {
            #pragma unroll
            for (int j = 0; j < 16; ++j) mycnt[cc[j]]++;
        }
        #pragma unroll
        for (int j = 0; j < 16; ++j)
            ssum[cc[j] * NDIM + dim] += xv[j];
    }
    for (; i < hi; i += 2) {
        int c = g_clusters[i];
        float x = X[(size_t)i * NDIM + dim];
        if (dim == 0) mycnt[c]++;
        ssum[c * NDIM + dim] += x;
    }
    __syncthreads();

    float* part = g_part[blockIdx.x];
    for (int k = tid; k < KCLUST * NDIM; k += 256)
        part[k] = sm_f[k] + sm_f[KCLUST * NDIM + k];
    if (tid < 128) {
        int c = scnt[tid] + scnt[128 + tid];
        if (c) atomicAdd(&g_counts[tid], c);
    }
}

// ---------------------------------------------------------------------------
__global__ void __launch_bounds__(128)
update_a_kernel(int iter) {
    if (*(volatile int*)&g_done) return;
    int k = blockIdx.x, j = threadIdx.x;
    int idx = k * NDIM + j;

    double ac[4] = {0, 0, 0, 0};
    #pragma unroll 1
    for (int b = 0; b < NBLK_ACC; b += 4)
        #pragma unroll
        for (int u = 0; u < 4; ++u) ac[u] += (double)g_part[b + u][idx];
    double s = (ac[0] + ac[1]) + (ac[2] + ac[3]);
    float sf = (float)s;

    int cnt = g_counts[k];
    float old = g_cent[idx];
    float newc = (cnt > 0) ? (sf / fmaxf((float)cnt, 1.0f)) : old;
    g_cent_new[idx] = newc;

    float d = newc - old;
    __shared__ float rb[128];
    rb[j] = d * d;
    __syncthreads();
    #pragma unroll
    for (int o = 64; o; o >>= 1) {
        if (j < o) rb[j] += rb[j + o];
        __syncthreads();
    }
    if (j == 0) {
        if (rb[0] < 1e-8f) atomicAdd(&g_conv[iter], 1);
        g_counts[k] = 0;
    }
}

__global__ void __launch_bounds__(128)
update_b_kernel(int iter) {
    if (*(volatile int*)&g_done) return;
    int k = blockIdx.x, j = threadIdx.x;
    int cv = g_conv[iter];
    if (cv == KCLUST) {
        if (k == 0 && j == 0) g_done = 1;
        return;
    }
    int idx = k * NDIM + j;
    float v = g_cent_new[idx];
    g_cent[idx] = v;
    __nv_bfloat16 hi = __float2bfloat16(v);
    g_chi[idx] = hi;
    g_clo[idx] = __float2bfloat16(v - __bfloat162float(hi));

    __shared__ double rb[128];
    rb[j] = (double)v * (double)v;
    __syncthreads();
    #pragma unroll
    for (int o = 64; o; o >>= 1) {
        if (j < o) rb[j] += rb[j + o];
        __syncthreads();
    }
    if (j == 0) g_csqf[k] = (float)rb[0];
}

// ---------------------------------------------------------------------------
__global__ void finalize_kernel(float* __restrict__ out, int m, int out_size) {
    int idx = blockIdx.x * 256 + threadIdx.x;
    const int nc = KCLUST * NDIM;
    if (out_size >= nc + m) {
        if (idx < nc) out[idx] = g_cent[idx];
        else if (idx < nc + m) out[idx] = (float)g_clusters[idx - nc];
    } else if (out_size == m) {
        if (idx < m) out[idx] = (float)g_clusters[idx];
    } else {
        if (idx < out_size && idx < nc) out[idx] = g_cent[idx];
    }
}

// ---------------------------------------------------------------------------
extern "C" void kernel_launch(void* const* d_in, const int* in_sizes, int n_in,
                              void* d_out, int out_size) {
    const float* X  = (const float*)d_in[0];
    const float* C0 = (const float*)d_in[1];
    int m = in_sizes[0] / NDIM;
    if (m > MAX_M) m = MAX_M;

    cudaFuncSetAttribute(assign_tc_kernel,
                         cudaFuncAttributeMaxDynamicSharedMemorySize,
                         ASSIGN_TC_SMEM);
    cudaFuncSetAttribute(accum_kernel,
                         cudaFuncAttributeMaxDynamicSharedMemorySize,
                         ACCUM_SMEM_BYTES);

    init_kernel<<<129, 128>>>(C0);
    xprep_kernel<<<(MAX_M + 7) / 8, 256>>>(X, m);

    int ablocks = (m + 127) / 128;
    for (int it = 0; it < MAXIT; ++it) {
        assign_tc_kernel<<<ablocks, 256, ASSIGN_TC_SMEM>>>(X, m);
        accum_kernel<<<NBLK_ACC, 256, ACCUM_SMEM_BYTES>>>(X, m);
        update_a_kernel<<<128, 128>>>(it);
        update_b_kernel<<<128, 128>>>(it);
    }

    int fb = (out_size + 255) / 256;
    if (fb < 1) fb = 1;
    finalize_kernel<<<fb, 256>>>((float*)d_out, m, out_size);
}

// round 8
// speedup vs baseline: 2.0267x; 1.5138x over previous
#include <cuda_runtime.h>
#include <cuda_bf16.h>
#include <cfloat>
#include <cstdint>

// ---------------------------------------------------------------------------
// K-means: X [m,128] fp32, centroids_init [128,128] fp32, K=128, 15 iters,
// tol=1e-4. Assignment via bf16-split tensor-core GEMM (3 logical passes)
// with in-block fp64 near-tie refinement. Segment sums read EXACT fp32 X
// (required: centroid error must stay ~1e-8 or assignment flips amplify),
// fp32 block partials in smem (2 independent groups), fp64 merge.
// ---------------------------------------------------------------------------

#define KCLUST 128
#define NDIM   128
#define MAXIT  15
#define MAX_M  100352
#define NBLK_ACC 148
#define TAU 4e-3f
#define APITCH 72   // bf16 pitch for 64-col smem tiles (conflict-free ldmatrix)

__device__ float  g_cent[KCLUST * NDIM];
__device__ float  g_cent_new[KCLUST * NDIM];
__device__ float  g_csqf[KCLUST];
__device__ float  g_part[NBLK_ACC][KCLUST * NDIM];
__device__ int    g_counts[KCLUST];
__device__ int    g_clusters[MAX_M];
__device__ float  g_xsq[MAX_M];
__device__ int    g_conv[MAXIT + 1];
__device__ int    g_done;

__device__ __nv_bfloat16 g_xhi[MAX_M * NDIM];
__device__ __nv_bfloat16 g_xlo[MAX_M * NDIM];
__device__ __nv_bfloat16 g_chi[KCLUST * NDIM];
__device__ __nv_bfloat16 g_clo[KCLUST * NDIM];

// ---------------------------------------------------------------------------
__global__ void init_kernel(const float* __restrict__ c0) {
    int b = blockIdx.x, t = threadIdx.x;
    if (b < 128) {
        int idx = b * 128 + t;
        float v = c0[idx];
        g_cent[idx] = v;
        __nv_bfloat16 hi = __float2bfloat16(v);
        g_chi[idx] = hi;
        g_clo[idx] = __float2bfloat16(v - __bfloat162float(hi));
        __shared__ double rb[128];
        rb[t] = (double)v * (double)v;
        __syncthreads();
        #pragma unroll
        for (int o = 64; o; o >>= 1) {
            if (t < o) rb[t] += rb[t + o];
            __syncthreads();
        }
        if (t == 0) g_csqf[b] = (float)rb[0];
    } else {
        if (t < KCLUST) g_counts[t] = 0;
        if (t < MAXIT + 1) g_conv[t] = 0;
        if (t == 0) g_done = 0;
    }
}

// ---------------------------------------------------------------------------
// One-time: fused x_sq (fp64->fp32) + bf16 split of X (+ zero padded rows).
// ---------------------------------------------------------------------------
__global__ void __launch_bounds__(256)
xprep_kernel(const float* __restrict__ X, int m) {
    int row = blockIdx.x * 8 + (threadIdx.x >> 5);
    int lane = threadIdx.x & 31;
    if (row >= MAX_M) return;
    __nv_bfloat162* hip = (__nv_bfloat162*)(g_xhi + (size_t)row * NDIM + lane * 4);
    __nv_bfloat162* lop = (__nv_bfloat162*)(g_xlo + (size_t)row * NDIM + lane * 4);
    if (row < m) {
        float4 v = *reinterpret_cast<const float4*>(&X[(size_t)row * NDIM + lane * 4]);
        float f[4] = {v.x, v.y, v.z, v.w};
        __nv_bfloat16 h[4], l[4];
        #pragma unroll
        for (int j = 0; j < 4; ++j) {
            h[j] = __float2bfloat16(f[j]);
            l[j] = __float2bfloat16(f[j] - __bfloat162float(h[j]));
        }
        hip[0] = __nv_bfloat162(h[0], h[1]);
        hip[1] = __nv_bfloat162(h[2], h[3]);
        lop[0] = __nv_bfloat162(l[0], l[1]);
        lop[1] = __nv_bfloat162(l[2], l[3]);
        double s = (double)v.x * v.x + (double)v.y * v.y +
                   (double)v.z * v.z + (double)v.w * v.w;
        #pragma unroll
        for (int o = 16; o; o >>= 1) s += __shfl_xor_sync(0xFFFFFFFFu, s, o);
        if (lane == 0) g_xsq[row] = (float)s;
    } else {
        __nv_bfloat162 z(__float2bfloat16(0.0f), __float2bfloat16(0.0f));
        hip[0] = z; hip[1] = z; lop[0] = z; lop[1] = z;
    }
}

// ---------------------------------------------------------------------------
// Assignment: bf16-split tensor-core GEMM + argmin + fused in-block fp64
// refinement of near-ties (replays reference fp32 op order, first-index-wins).
// ---------------------------------------------------------------------------
#define LDSM_X4(r0, r1, r2, r3, addr) \
    asm volatile("ldmatrix.sync.aligned.m8n8.x4.shared.b16 {%0,%1,%2,%3}, [%4];" \
        : "=r"(r0), "=r"(r1), "=r"(r2), "=r"(r3) : "r"(addr))

#define MMA16816(d, a, b0, b1) \
    asm volatile("mma.sync.aligned.m16n8k16.row.col.f32.bf16.bf16.f32 " \
        "{%0,%1,%2,%3},{%4,%5,%6,%7},{%8,%9},{%0,%1,%2,%3};" \
        : "+f"(d[0]), "+f"(d[1]), "+f"(d[2]), "+f"(d[3]) \
        : "r"(a[0]), "r"(a[1]), "r"(a[2]), "r"(a[3]), "r"(b0), "r"(b1))

#define TILE_B (128 * APITCH)
#define ASSIGN_TC_SMEM ((4 + 2) * TILE_B * 2 + 1024)

__global__ void __launch_bounds__(256, 2)
assign_tc_kernel(const float* __restrict__ X, int m) {
    if (*(volatile int*)&g_done) return;

    extern __shared__ char sm8[];
    __nv_bfloat16* Cs = (__nv_bfloat16*)sm8;         // 4 centroid chunks
    __nv_bfloat16* As = Cs + 4 * TILE_B;             // 2 A buffers
    float* scs = (float*)(As + 2 * TILE_B);
    float* sxq = scs + 128;
    float* redD = (float*)sm8;                       // overlays Cs post-GEMM
    int*   redI = (int*)(sm8 + 2048);
    float* redS = (float*)(sm8 + 4096);

    __shared__ int   s_nf;
    __shared__ int   s_fl[128];
    __shared__ float sD[128];
    __shared__ int   sI[128];

    const int tid = threadIdx.x;
    const int lane = tid & 31;
    const int wid = tid >> 5;
    const int wm = wid & 3;
    const int wn = wid >> 2;
    const int p0 = blockIdx.x * 128;

    if (tid == 0) s_nf = 0;
    if (tid < 128) {
        scs[tid] = g_csqf[tid];
        int p = p0 + tid;
        sxq[tid] = (p < m) ? g_xsq[p] : 0.0f;
    }

    #pragma unroll
    for (int ch = 0; ch < 4; ++ch) {
        const __nv_bfloat16* Bp = (ch < 2) ? g_chi : g_clo;
        int kc = (ch & 1) * 64;
        #pragma unroll
        for (int i = 0; i < 4; ++i) {
            int lin = tid + i * 256;
            int row = lin >> 3, c8 = lin & 7;
            uint4 vb = *(const uint4*)(Bp + row * 128 + kc + c8 * 8);
            *(uint4*)(Cs + ch * TILE_B + row * APITCH + c8 * 8) = vb;
        }
    }

    uint4 nxt[4];
    {
        #pragma unroll
        for (int i = 0; i < 4; ++i) {
            int lin = tid + i * 256;
            int row = lin >> 3, c8 = lin & 7;
            nxt[i] = *(const uint4*)(g_xhi + (size_t)(p0 + row) * 128 + c8 * 8);
        }
        #pragma unroll
        for (int i = 0; i < 4; ++i) {
            int lin = tid + i * 256;
            int row = lin >> 3, c8 = lin & 7;
            *(uint4*)(As + row * APITCH + c8 * 8) = nxt[i];
        }
    }
    __syncthreads();

    const int q = lane >> 3;
    const int r = lane & 7;
    uint32_t asBase = (uint32_t)__cvta_generic_to_shared(As);
    uint32_t csBase = (uint32_t)__cvta_generic_to_shared(Cs);
    uint32_t aoff[2];
    #pragma unroll
    for (int mi = 0; mi < 2; ++mi)
        aoff[mi] = asBase +
            (uint32_t)(((wm * 32 + mi * 16 + (q & 1) * 8 + r) * APITCH + (q >> 1) * 8) * 2);
    uint32_t boff[4];
    #pragma unroll
    for (int nip = 0; nip < 4; ++nip)
        boff[nip] = csBase +
            (uint32_t)(((wn * 64 + nip * 16 + (q >> 1) * 8 + r) * APITCH + (q & 1) * 8) * 2);

    float acc[2][8][4];
    #pragma unroll
    for (int mi = 0; mi < 2; ++mi)
        #pragma unroll
        for (int ni = 0; ni < 8; ++ni)
            #pragma unroll
            for (int u = 0; u < 4; ++u) acc[mi][ni][u] = 0.0f;

    const uint32_t TILE_BYTES = TILE_B * 2;

    #pragma unroll 1
    for (int s = 0; s < 4; ++s) {
        if (s < 3) {
            const __nv_bfloat16* Ap = (s + 1 < 2) ? g_xhi : g_xlo;
            int kc = ((s + 1) & 1) * 64;
            #pragma unroll
            for (int i = 0; i < 4; ++i) {
                int lin = tid + i * 256;
                int row = lin >> 3, c8 = lin & 7;
                nxt[i] = *(const uint4*)(Ap + (size_t)(p0 + row) * 128 + kc + c8 * 8);
            }
        }

        const uint32_t abuf = (uint32_t)(s & 1) * TILE_BYTES;
        const uint32_t hiB = (uint32_t)(s & 1) * TILE_BYTES;
        const uint32_t loB = (uint32_t)(2 + (s & 1)) * TILE_BYTES;
        const bool doLo = (s < 2);

        #pragma unroll
        for (int ks = 0; ks < 4; ++ks) {
            uint32_t a[2][4];
            #pragma unroll
            for (int mi = 0; mi < 2; ++mi)
                LDSM_X4(a[mi][0], a[mi][1], a[mi][2], a[mi][3],
                        aoff[mi] + abuf + ks * 32);
            uint32_t b[4][4];
            #pragma unroll
            for (int nip = 0; nip < 4; ++nip)
                LDSM_X4(b[nip][0], b[nip][1], b[nip][2], b[nip][3],
                        boff[nip] + hiB + ks * 32);
            #pragma unroll
            for (int mi = 0; mi < 2; ++mi)
                #pragma unroll
                for (int nip = 0; nip < 4; ++nip) {
                    MMA16816(acc[mi][nip * 2 + 0], a[mi], b[nip][0], b[nip][1]);
                    MMA16816(acc[mi][nip * 2 + 1], a[mi], b[nip][2], b[nip][3]);
                }
            if (doLo) {
                #pragma unroll
                for (int nip = 0; nip < 4; ++nip)
                    LDSM_X4(b[nip][0], b[nip][1], b[nip][2], b[nip][3],
                            boff[nip] + loB + ks * 32);
                #pragma unroll
                for (int mi = 0; mi < 2; ++mi)
                    #pragma unroll
                    for (int nip = 0; nip < 4; ++nip) {
                        MMA16816(acc[mi][nip * 2 + 0], a[mi], b[nip][0], b[nip][1]);
                        MMA16816(acc[mi][nip * 2 + 1], a[mi], b[nip][2], b[nip][3]);
                    }
            }
        }

        if (s < 3) {
            #pragma unroll
            for (int i = 0; i < 4; ++i) {
                int lin = tid + i * 256;
                int row = lin >> 3, c8 = lin & 7;
                *(uint4*)(As + ((s + 1) & 1) * TILE_B + row * APITCH + c8 * 8) = nxt[i];
            }
        }
        __syncthreads();
    }

    const int r0 = lane >> 2;
    const int c0 = (lane & 3) * 2;
    float bd[4], sd[4]; int bi[4];
    #pragma unroll
    for (int mi = 0; mi < 2; ++mi) {
        #pragma unroll
        for (int h = 0; h < 2; ++h) {
            int qq = mi * 2 + h;
            int pl = wm * 32 + mi * 16 + h * 8 + r0;
            float xq = sxq[pl];
            float b_ = FLT_MAX, s_ = FLT_MAX; int i_ = 0;
            #pragma unroll
            for (int ni = 0; ni < 8; ++ni) {
                #pragma unroll
                for (int u = 0; u < 2; ++u) {
                    int n = wn * 64 + ni * 8 + c0 + u;
                    float d2 = (xq - 2.0f * acc[mi][ni][h * 2 + u]) + scs[n];
                    if (d2 < b_) { s_ = b_; b_ = d2; i_ = n; }
                    else if (d2 < s_) s_ = d2;
                }
            }
            bd[qq] = b_; sd[qq] = s_; bi[qq] = i_;
        }
    }
    #pragma unroll
    for (int off = 1; off <= 2; off <<= 1) {
        #pragma unroll
        for (int qq = 0; qq < 4; ++qq) {
            float obd = __shfl_xor_sync(0xFFFFFFFFu, bd[qq], off);
            int   obi = __shfl_xor_sync(0xFFFFFFFFu, bi[qq], off);
            float osd = __shfl_xor_sync(0xFFFFFFFFu, sd[qq], off);
            bool take = (obd < bd[qq]) || (obd == bd[qq] && obi < bi[qq]);
            float loser = take ? bd[qq] : obd;
            sd[qq] = fminf(fminf(sd[qq], osd), loser);
            if (take) { bd[qq] = obd; bi[qq] = obi; }
        }
    }
    if ((lane & 3) == 0) {
        #pragma unroll
        for (int qq = 0; qq < 4; ++qq) {
            int pl = wm * 32 + (qq >> 1) * 16 + (qq & 1) * 8 + r0;
            redD[pl * 2 + wn] = bd[qq];
            redI[pl * 2 + wn] = bi[qq];
            redS[pl * 2 + wn] = sd[qq];
        }
    }
    __syncthreads();

    if (tid < 128) {
        int p = p0 + tid;
        if (p < m) {
            float b_ = redD[tid * 2], s_ = redS[tid * 2];
            int i_ = redI[tid * 2];
            float od = redD[tid * 2 + 1], os = redS[tid * 2 + 1];
            int oi = redI[tid * 2 + 1];
            bool take = (od < b_) || (od == b_ && oi < i_);
            float loser = take ? b_ : od;
            s_ = fminf(fminf(s_, os), loser);
            if (take) { b_ = od; i_ = oi; }
            g_clusters[p] = i_;
            if (s_ - b_ < TAU) {
                int w = atomicAdd(&s_nf, 1);
                s_fl[w] = tid;
            }
        }
    }
    __syncthreads();

    int nf = s_nf;
    for (int f = 0; f < nf; ++f) {
        int pl = s_fl[f];
        int p = p0 + pl;
        if (tid < 128) {
            const float* xr = X + (size_t)p * NDIM;
            const float* cr = g_cent + tid * NDIM;
            double ac[8] = {0, 0, 0, 0, 0, 0, 0, 0};
            #pragma unroll
            for (int k = 0; k < 16; ++k)
                #pragma unroll
                for (int j = 0; j < 8; ++j)
                    ac[j] += (double)xr[k * 8 + j] * (double)cr[k * 8 + j];
            double dot = ((ac[0] + ac[1]) + (ac[2] + ac[3])) +
                         ((ac[4] + ac[5]) + (ac[6] + ac[7]));
            float dotf = (float)dot;
            float t = sxq[pl] - 2.0f * dotf;
            float d2 = t + scs[tid];
            sD[tid] = d2; sI[tid] = tid;
        }
        __syncthreads();
        #pragma unroll
        for (int o = 64; o; o >>= 1) {
            if (tid < o) {
                float d = sD[tid + o]; int cc = sI[tid + o];
                if (d < sD[tid] || (d == sD[tid] && cc < sI[tid])) {
                    sD[tid] = d; sI[tid] = cc;
                }
            }
            __syncthreads();
        }
        if (tid == 0) g_clusters[p] = sI[0];
        __syncthreads();
    }
}

// ---------------------------------------------------------------------------
// Segment accumulation: EXACT fp32 X reads, two private smem accumulator
// groups (race-free +=), 16-point batches for MLP, fp32 block partials.
// ---------------------------------------------------------------------------
#define ACCUM_SMEM_BYTES (2 * KCLUST * NDIM * 4 + 2 * KCLUST * 4)

__global__ void __launch_bounds__(256)
accum_kernel(const float* __restrict__ X, int m) {
    if (*(volatile int*)&g_done) return;

    extern __shared__ float sm_f[];                 // 2 x 16384 floats
    int* scnt = (int*)(sm_f + 2 * KCLUST * NDIM);   // 2 x 128 ints

    const int tid = threadIdx.x;
    const int grp = tid >> 7;          // 0 / 1
    const int dim = tid & 127;
    float* ssum = sm_f + grp * (KCLUST * NDIM);
    int* mycnt = scnt + grp * 128;

    for (int i = tid; i < 2 * KCLUST * NDIM; i += 256) sm_f[i] = 0.0f;
    scnt[tid] = 0;
    __syncthreads();

    int chunk = (m + NBLK_ACC - 1) / NBLK_ACC;
    int lo = blockIdx.x * chunk;
    int hi = lo + chunk; if (hi > m) hi = m;

    int i = lo + grp;
    for (; i + 30 < hi; i += 32) {      // 16 points per group, stride 2
        int cc[16]; float xv[16];
        #pragma unroll
        for (int j = 0; j < 16; ++j) cc[j] = g_clusters[i + 2 * j];
        #pragma unroll
        for (int j = 0; j < 16; ++j)
            xv[j] = X[(size_t)(i + 2 * j) * NDIM + dim];
        if (dim == 0) {
            #pragma unroll
            for (int j = 0; j < 16; ++j) mycnt[cc[j]]++;
        }
        #pragma unroll
        for (int j = 0; j < 16; ++j)
            ssum[cc[j] * NDIM + dim] += xv[j];
    }
    for (; i < hi; i += 2) {
        int c = g_clusters[i];
        float x = X[(size_t)i * NDIM + dim];
        if (dim == 0) mycnt[c]++;
        ssum[c * NDIM + dim] += x;
    }
    __syncthreads();

    float* part = g_part[blockIdx.x];
    for (int k = tid; k < KCLUST * NDIM; k += 256)
        part[k] = sm_f[k] + sm_f[KCLUST * NDIM + k];
    if (tid < 128) {
        int c = scnt[tid] + scnt[128 + tid];
        if (c) atomicAdd(&g_counts[tid], c);
    }
}

// ---------------------------------------------------------------------------
__global__ void __launch_bounds__(128)
update_a_kernel(int iter) {
    if (*(volatile int*)&g_done) return;
    int k = blockIdx.x, j = threadIdx.x;
    int idx = k * NDIM + j;

    double ac[4] = {0, 0, 0, 0};
    #pragma unroll 1
    for (int b = 0; b < NBLK_ACC; b += 4)
        #pragma unroll
        for (int u = 0; u < 4; ++u) ac[u] += (double)g_part[b + u][idx];
    double s = (ac[0] + ac[1]) + (ac[2] + ac[3]);
    float sf = (float)s;

    int cnt = g_counts[k];
    float old = g_cent[idx];
    float newc = (cnt > 0) ? (sf / fmaxf((float)cnt, 1.0f)) : old;
    g_cent_new[idx] = newc;

    float d = newc - old;
    __shared__ float rb[128];
    rb[j] = d * d;
    __syncthreads();
    #pragma unroll
    for (int o = 64; o; o >>= 1) {
        if (j < o) rb[j] += rb[j + o];
        __syncthreads();
    }
    if (j == 0) {
        if (rb[0] < 1e-8f) atomicAdd(&g_conv[iter], 1);
        g_counts[k] = 0;
    }
}

__global__ void __launch_bounds__(128)
update_b_kernel(int iter) {
    if (*(volatile int*)&g_done) return;
    int k = blockIdx.x, j = threadIdx.x;
    int cv = g_conv[iter];
    if (cv == KCLUST) {
        if (k == 0 && j == 0) g_done = 1;
        return;
    }
    int idx = k * NDIM + j;
    float v = g_cent_new[idx];
    g_cent[idx] = v;
    __nv_bfloat16 hi = __float2bfloat16(v);
    g_chi[idx] = hi;
    g_clo[idx] = __float2bfloat16(v - __bfloat162float(hi));

    __shared__ double rb[128];
    rb[j] = (double)v * (double)v;
    __syncthreads();
    #pragma unroll
    for (int o = 64; o; o >>= 1) {
        if (j < o) rb[j] += rb[j + o];
        __syncthreads();
    }
    if (j == 0) g_csqf[k] = (float)rb[0];
}

// ---------------------------------------------------------------------------
__global__ void finalize_kernel(float* __restrict__ out, int m, int out_size) {
    int idx = blockIdx.x * 256 + threadIdx.x;
    const int nc = KCLUST * NDIM;
    if (out_size >= nc + m) {
        if (idx < nc) out[idx] = g_cent[idx];
        else if (idx < nc + m) out[idx] = (float)g_clusters[idx - nc];
    } else if (out_size == m) {
        if (idx < m) out[idx] = (float)g_clusters[idx];
    } else {
        if (idx < out_size && idx < nc) out[idx] = g_cent[idx];
    }
}

// ---------------------------------------------------------------------------
extern "C" void kernel_launch(void* const* d_in, const int* in_sizes, int n_in,
                              void* d_out, int out_size) {
    const float* X  = (const float*)d_in[0];
    const float* C0 = (const float*)d_in[1];
    int m = in_sizes[0] / NDIM;
    if (m > MAX_M) m = MAX_M;

    cudaFuncSetAttribute(assign_tc_kernel,
                         cudaFuncAttributeMaxDynamicSharedMemorySize,
                         ASSIGN_TC_SMEM);
    cudaFuncSetAttribute(accum_kernel,
                         cudaFuncAttributeMaxDynamicSharedMemorySize,
                         ACCUM_SMEM_BYTES);

    init_kernel<<<129, 128>>>(C0);
    xprep_kernel<<<(MAX_M + 7) / 8, 256>>>(X, m);

    int ablocks = (m + 127) / 128;
    for (int it = 0; it < MAXIT; ++it) {
        assign_tc_kernel<<<ablocks, 256, ASSIGN_TC_SMEM>>>(X, m);
        accum_kernel<<<NBLK_ACC, 256, ACCUM_SMEM_BYTES>>>(X, m);
        update_a_kernel<<<128, 128>>>(it);
        update_b_kernel<<<128, 128>>>(it);
    }

    int fb = (out_size + 255) / 256;
    if (fb < 1) fb = 1;
    finalize_kernel<<<fb, 256>>>((float*)d_out, m, out_size);
}